// round 1
// baseline (speedup 1.0000x reference)
#include <cuda_runtime.h>
#include <math.h>

#define D_MODEL 1024
#define D_FF    2048
#define BATCH   4
#define SEQ     2048
#define HEADS   16
#define DK      64
#define ROWS    (BATCH * SEQ)   // 8192

// ---------------- scratch (no allocs allowed -> __device__ globals) ----------
__device__ float g_x2  [ROWS * D_MODEL];
__device__ float g_q   [ROWS * D_MODEL];
__device__ float g_k   [ROWS * D_MODEL];
__device__ float g_v   [ROWS * D_MODEL];
__device__ float g_attn[ROWS * D_MODEL];
__device__ float g_xres[ROWS * D_MODEL];
__device__ float g_h   [ROWS * D_FF];

// ---------------- LayerNorm: alpha*(x-mu)/(std+eps)+bias, std unbiased ------
__global__ void __launch_bounds__(256) norm_kernel(
    const float* __restrict__ x, const float* __restrict__ alpha,
    const float* __restrict__ bias, float* __restrict__ out)
{
    const int row = blockIdx.x;
    const int t = threadIdx.x;
    const float4* xr = (const float4*)(x + (size_t)row * D_MODEL);
    float4 v = xr[t];
    float s  = v.x + v.y + v.z + v.w;
    float ss = v.x*v.x + v.y*v.y + v.z*v.z + v.w*v.w;
    #pragma unroll
    for (int o = 16; o; o >>= 1) {
        s  += __shfl_xor_sync(0xffffffffu, s, o);
        ss += __shfl_xor_sync(0xffffffffu, ss, o);
    }
    __shared__ float rs[8], rss[8];
    __shared__ float s_mu, s_inv;
    const int w = t >> 5, l = t & 31;
    if (l == 0) { rs[w] = s; rss[w] = ss; }
    __syncthreads();
    if (t == 0) {
        float S = 0.f, SS = 0.f;
        #pragma unroll
        for (int i = 0; i < 8; i++) { S += rs[i]; SS += rss[i]; }
        float mu  = S * (1.0f / D_MODEL);
        float var = (SS - (float)D_MODEL * mu * mu) * (1.0f / (D_MODEL - 1));
        s_mu  = mu;
        s_inv = 1.0f / (sqrtf(fmaxf(var, 0.f)) + 1e-6f);
    }
    __syncthreads();
    const float mu = s_mu, inv = s_inv;
    float4 av = ((const float4*)alpha)[t];
    float4 bv = ((const float4*)bias)[t];
    float4 o;
    o.x = av.x * (v.x - mu) * inv + bv.x;
    o.y = av.y * (v.y - mu) * inv + bv.y;
    o.z = av.z * (v.z - mu) * inv + bv.z;
    o.w = av.w * (v.w - mu) * inv + bv.w;
    ((float4*)(out + (size_t)row * D_MODEL))[t] = o;
}

// ---------------- SGEMM: C[M,N] = A[M,K] @ W[N,K]^T + bias (+relu)(+res) ----
template<bool RELU, bool RES>
__global__ void __launch_bounds__(256) gemm_kernel(
    const float* __restrict__ A, const float* __restrict__ W,
    const float* __restrict__ bias, const float* __restrict__ R,
    float* __restrict__ C, int M, int N, int K)
{
    __shared__ float As[8][128];
    __shared__ float Bs[8][128];
    const int m0 = blockIdx.y * 128, n0 = blockIdx.x * 128;
    const int tid = threadIdx.x;
    const int tx = tid & 15, ty = tid >> 4;
    const int lrow = tid >> 1, lc4 = (tid & 1) * 4;
    const float* Ap = A + (size_t)(m0 + lrow) * K + lc4;
    const float* Wp = W + (size_t)(n0 + lrow) * K + lc4;
    float acc[8][8] = {};
    for (int k0 = 0; k0 < K; k0 += 8) {
        float4 a = *(const float4*)(Ap + k0);
        float4 b = *(const float4*)(Wp + k0);
        As[lc4 + 0][lrow] = a.x; As[lc4 + 1][lrow] = a.y;
        As[lc4 + 2][lrow] = a.z; As[lc4 + 3][lrow] = a.w;
        Bs[lc4 + 0][lrow] = b.x; Bs[lc4 + 1][lrow] = b.y;
        Bs[lc4 + 2][lrow] = b.z; Bs[lc4 + 3][lrow] = b.w;
        __syncthreads();
        #pragma unroll
        for (int kk = 0; kk < 8; kk++) {
            float4 a0 = *(const float4*)&As[kk][ty * 8];
            float4 a1 = *(const float4*)&As[kk][ty * 8 + 4];
            float4 b0 = *(const float4*)&Bs[kk][tx * 8];
            float4 b1 = *(const float4*)&Bs[kk][tx * 8 + 4];
            float ar[8] = {a0.x, a0.y, a0.z, a0.w, a1.x, a1.y, a1.z, a1.w};
            float br[8] = {b0.x, b0.y, b0.z, b0.w, b1.x, b1.y, b1.z, b1.w};
            #pragma unroll
            for (int i = 0; i < 8; i++)
                #pragma unroll
                for (int j = 0; j < 8; j++)
                    acc[i][j] += ar[i] * br[j];
        }
        __syncthreads();
    }
    #pragma unroll
    for (int i = 0; i < 8; i++) {
        const int m = m0 + ty * 8 + i;
        float* Cr = C + (size_t)m * N + n0;
        const float* Rr = RES ? (R + (size_t)m * N + n0) : nullptr;
        #pragma unroll
        for (int j = 0; j < 8; j++) {
            float c = acc[i][j] + bias[n0 + tx * 8 + j];
            if (RELU) c = fmaxf(c, 0.f);
            if (RES)  c += Rr[tx * 8 + j];
            Cr[tx * 8 + j] = c;
        }
    }
}

// ---------------- flash attention: one CTA per (b, h, 64-query tile) --------
#define FL_SMEM_FLOATS (64*64 + 3*64*65 + 3*64 + 64)
#define FL_SMEM_BYTES  (FL_SMEM_FLOATS * 4)

__global__ void __launch_bounds__(256) flash_kernel(
    const float* __restrict__ Q, const float* __restrict__ K,
    const float* __restrict__ V, const int* __restrict__ mask,
    float* __restrict__ O)
{
    const int qt = blockIdx.x, h = blockIdx.y, b = blockIdx.z;
    const int tid = threadIdx.x;
    const int tx = tid & 15, ty = tid >> 4;
    extern __shared__ float sm[];
    float* Qs   = sm;                 // [64][64]
    float* Ks   = Qs + 64 * 64;       // [64][65]
    float* Vs   = Ks + 64 * 65;       // [64][65]
    float* Ps   = Vs + 64 * 65;       // [64][65]
    float* mrow = Ps + 64 * 65;       // [64]
    float* lrow = mrow + 64;
    float* srow = lrow + 64;
    int*   mkf  = (int*)(srow + 64);

    const int q0 = qt * 64;
    const size_t rb = (size_t)b * SEQ;

    // load Q tile (coalesced float4)
    #pragma unroll
    for (int l = 0; l < 4; l++) {
        int idx = tid + l * 256;              // 0..1023 float4s
        int r = idx >> 4, c4 = (idx & 15) << 2;
        float4 qv = *(const float4*)(Q + (rb + q0 + r) * D_MODEL + h * DK + c4);
        Qs[r * 64 + c4 + 0] = qv.x; Qs[r * 64 + c4 + 1] = qv.y;
        Qs[r * 64 + c4 + 2] = qv.z; Qs[r * 64 + c4 + 3] = qv.w;
    }
    if (tid < 64) { mrow[tid] = -1e30f; lrow[tid] = 0.f; }

    float acc[4][4] = {};

    for (int kt = 0; kt < SEQ / 64; kt++) {
        const int k0 = kt * 64;
        __syncthreads();   // protect smem from previous iteration's readers
        #pragma unroll
        for (int l = 0; l < 4; l++) {
            int idx = tid + l * 256;
            int r = idx >> 4, c4 = (idx & 15) << 2;
            float4 kv = *(const float4*)(K + (rb + k0 + r) * D_MODEL + h * DK + c4);
            Ks[r * 65 + c4 + 0] = kv.x; Ks[r * 65 + c4 + 1] = kv.y;
            Ks[r * 65 + c4 + 2] = kv.z; Ks[r * 65 + c4 + 3] = kv.w;
            float4 vv = *(const float4*)(V + (rb + k0 + r) * D_MODEL + h * DK + c4);
            Vs[r * 65 + c4 + 0] = vv.x; Vs[r * 65 + c4 + 1] = vv.y;
            Vs[r * 65 + c4 + 2] = vv.z; Vs[r * 65 + c4 + 3] = vv.w;
        }
        if (tid < 64) mkf[tid] = mask[b * SEQ + k0 + tid];
        __syncthreads();

        // scores: S = Q @ K^T * 0.125  (4x4 register block per thread)
        float s[4][4] = {};
        #pragma unroll 16
        for (int kk = 0; kk < 64; kk++) {
            float qr[4], kr[4];
            #pragma unroll
            for (int i = 0; i < 4; i++) qr[i] = Qs[(ty * 4 + i) * 64 + kk];
            #pragma unroll
            for (int j = 0; j < 4; j++) kr[j] = Ks[(tx * 4 + j) * 65 + kk];
            #pragma unroll
            for (int i = 0; i < 4; i++)
                #pragma unroll
                for (int j = 0; j < 4; j++)
                    s[i][j] += qr[i] * kr[j];
        }
        #pragma unroll
        for (int i = 0; i < 4; i++)
            #pragma unroll
            for (int j = 0; j < 4; j++) {
                float val = s[i][j] * 0.125f;
                if (mkf[tx * 4 + j] == 1) val = -1e30f;
                Ps[(ty * 4 + i) * 65 + tx * 4 + j] = val;
            }
        __syncthreads();

        // online softmax: 4 lanes per query row (quad shuffle reduce)
        {
            const int q = tid >> 2, sg = tid & 3;
            const float m_old = mrow[q];
            float mx = m_old;
            #pragma unroll
            for (int jj = 0; jj < 16; jj++)
                mx = fmaxf(mx, Ps[q * 65 + sg * 16 + jj]);
            mx = fmaxf(mx, __shfl_xor_sync(0xffffffffu, mx, 1));
            mx = fmaxf(mx, __shfl_xor_sync(0xffffffffu, mx, 2));
            float sum = 0.f;
            #pragma unroll
            for (int jj = 0; jj < 16; jj++) {
                float p = __expf(Ps[q * 65 + sg * 16 + jj] - mx);
                Ps[q * 65 + sg * 16 + jj] = p;
                sum += p;
            }
            sum += __shfl_xor_sync(0xffffffffu, sum, 1);
            sum += __shfl_xor_sync(0xffffffffu, sum, 2);
            if (sg == 0) {
                float corr = __expf(m_old - mx);
                lrow[q] = lrow[q] * corr + sum;
                mrow[q] = mx;
                srow[q] = corr;
            }
        }
        __syncthreads();

        // rescale accumulators + P @ V
        float sc[4];
        #pragma unroll
        for (int i = 0; i < 4; i++) sc[i] = srow[ty * 4 + i];
        #pragma unroll
        for (int i = 0; i < 4; i++)
            #pragma unroll
            for (int d = 0; d < 4; d++) acc[i][d] *= sc[i];
        #pragma unroll 8
        for (int j = 0; j < 64; j++) {
            float pr[4], vr[4];
            #pragma unroll
            for (int i = 0; i < 4; i++) pr[i] = Ps[(ty * 4 + i) * 65 + j];
            #pragma unroll
            for (int d = 0; d < 4; d++) vr[d] = Vs[j * 65 + tx * 4 + d];
            #pragma unroll
            for (int i = 0; i < 4; i++)
                #pragma unroll
                for (int d = 0; d < 4; d++)
                    acc[i][d] += pr[i] * vr[d];
        }
    }

    // epilogue: divide by l, write concat layout [(b,s), h*64+d]
    #pragma unroll
    for (int i = 0; i < 4; i++) {
        const float inv = 1.0f / lrow[ty * 4 + i];
        float4 o;
        o.x = acc[i][0] * inv; o.y = acc[i][1] * inv;
        o.z = acc[i][2] * inv; o.w = acc[i][3] * inv;
        *(float4*)(O + (rb + q0 + ty * 4 + i) * D_MODEL + h * DK + tx * 4) = o;
    }
}

// ---------------- orchestration ---------------------------------------------
extern "C" void kernel_launch(void* const* d_in, const int* in_sizes, int n_in,
                              void* d_out, int out_size)
{
    const float* x      = (const float*)d_in[0];
    const int*   mask   = (const int*)  d_in[1];
    const float* alpha1 = (const float*)d_in[2];
    const float* bias1  = (const float*)d_in[3];
    const float* alpha2 = (const float*)d_in[4];
    const float* bias2  = (const float*)d_in[5];
    const float* Wq = (const float*)d_in[6];   const float* bq = (const float*)d_in[7];
    const float* Wk = (const float*)d_in[8];   const float* bk = (const float*)d_in[9];
    const float* Wv = (const float*)d_in[10];  const float* bv = (const float*)d_in[11];
    const float* Wo = (const float*)d_in[12];  const float* bo = (const float*)d_in[13];
    const float* W1 = (const float*)d_in[14];  const float* b1 = (const float*)d_in[15];
    const float* W2 = (const float*)d_in[16];  const float* b2 = (const float*)d_in[17];
    float* out = (float*)d_out;

    float *x2, *q, *k, *v, *attn, *xres, *hbuf;
    cudaGetSymbolAddress((void**)&x2,   g_x2);
    cudaGetSymbolAddress((void**)&q,    g_q);
    cudaGetSymbolAddress((void**)&k,    g_k);
    cudaGetSymbolAddress((void**)&v,    g_v);
    cudaGetSymbolAddress((void**)&attn, g_attn);
    cudaGetSymbolAddress((void**)&xres, g_xres);
    cudaGetSymbolAddress((void**)&hbuf, g_h);

    cudaFuncSetAttribute(flash_kernel,
                         cudaFuncAttributeMaxDynamicSharedMemorySize,
                         FL_SMEM_BYTES);

    const dim3 gProj(D_MODEL / 128, ROWS / 128);   // (8, 64)
    const dim3 gFF1 (D_FF    / 128, ROWS / 128);   // (16, 64)

    // x2 = norm1(x)
    norm_kernel<<<ROWS, 256>>>(x, alpha1, bias1, x2);
    // q, k, v projections
    gemm_kernel<false, false><<<gProj, 256>>>(x2, Wq, bq, nullptr, q, ROWS, D_MODEL, D_MODEL);
    gemm_kernel<false, false><<<gProj, 256>>>(x2, Wk, bk, nullptr, k, ROWS, D_MODEL, D_MODEL);
    gemm_kernel<false, false><<<gProj, 256>>>(x2, Wv, bv, nullptr, v, ROWS, D_MODEL, D_MODEL);
    // attention
    flash_kernel<<<dim3(SEQ / 64, HEADS, BATCH), 256, FL_SMEM_BYTES>>>(q, k, v, mask, attn);
    // xres = x + attn @ Wo^T + bo
    gemm_kernel<false, true ><<<gProj, 256>>>(attn, Wo, bo, x, xres, ROWS, D_MODEL, D_MODEL);
    // x2 = norm2(xres)
    norm_kernel<<<ROWS, 256>>>(xres, alpha2, bias2, x2);
    // h = relu(x2 @ W1^T + b1)
    gemm_kernel<true,  false><<<gFF1, 256>>>(x2, W1, b1, nullptr, hbuf, ROWS, D_FF, D_MODEL);
    // out = xres + h @ W2^T + b2
    gemm_kernel<false, true ><<<gProj, 256>>>(hbuf, W2, b2, xres, out, ROWS, D_MODEL, D_FF);
}

// round 2
// speedup vs baseline: 1.7612x; 1.7612x over previous
#include <cuda_runtime.h>
#include <math.h>

#define D_MODEL 1024
#define D_FF    2048
#define BATCH   4
#define SEQ     2048
#define HEADS   16
#define DK      64
#define ROWS    (BATCH * SEQ)   // 8192

// ---------------- scratch (no allocs allowed -> __device__ globals) ----------
__device__ float g_x2  [ROWS * D_MODEL];
__device__ float g_q   [ROWS * D_MODEL];
__device__ float g_k   [ROWS * D_MODEL];
__device__ float g_v   [ROWS * D_MODEL];
__device__ float g_attn[ROWS * D_MODEL];
__device__ float g_xres[ROWS * D_MODEL];
__device__ float g_h   [ROWS * D_FF];

// ---------------- LayerNorm: alpha*(x-mu)/(std+eps)+bias, std unbiased ------
__global__ void __launch_bounds__(256) norm_kernel(
    const float* __restrict__ x, const float* __restrict__ alpha,
    const float* __restrict__ bias, float* __restrict__ out)
{
    const int row = blockIdx.x;
    const int t = threadIdx.x;
    const float4* xr = (const float4*)(x + (size_t)row * D_MODEL);
    float4 v = xr[t];
    float s  = v.x + v.y + v.z + v.w;
    float ss = v.x*v.x + v.y*v.y + v.z*v.z + v.w*v.w;
    #pragma unroll
    for (int o = 16; o; o >>= 1) {
        s  += __shfl_xor_sync(0xffffffffu, s, o);
        ss += __shfl_xor_sync(0xffffffffu, ss, o);
    }
    __shared__ float rs[8], rss[8];
    __shared__ float s_mu, s_inv;
    const int w = t >> 5, l = t & 31;
    if (l == 0) { rs[w] = s; rss[w] = ss; }
    __syncthreads();
    if (t == 0) {
        float S = 0.f, SS = 0.f;
        #pragma unroll
        for (int i = 0; i < 8; i++) { S += rs[i]; SS += rss[i]; }
        float mu  = S * (1.0f / D_MODEL);
        float var = (SS - (float)D_MODEL * mu * mu) * (1.0f / (D_MODEL - 1));
        s_mu  = mu;
        s_inv = 1.0f / (sqrtf(fmaxf(var, 0.f)) + 1e-6f);
    }
    __syncthreads();
    const float mu = s_mu, inv = s_inv;
    float4 av = ((const float4*)alpha)[t];
    float4 bv = ((const float4*)bias)[t];
    float4 o;
    o.x = av.x * (v.x - mu) * inv + bv.x;
    o.y = av.y * (v.y - mu) * inv + bv.y;
    o.z = av.z * (v.z - mu) * inv + bv.z;
    o.w = av.w * (v.w - mu) * inv + bv.w;
    ((float4*)(out + (size_t)row * D_MODEL))[t] = o;
}

// ---------------- tf32 tensor-core GEMM --------------------------------------
// C[M,N] = A[M,K] @ W[N,K]^T + bias (+relu) (+residual)
// 128x128x32 CTA tile, 8 warps (2 M x 4 N), warp tile 64x32, mma.m16n8k8 tf32.
// smem rows padded to 36 floats: (36 mod 32)=4 makes fragment reads
// (lane/4)*4 + (lane%4) cover all 32 banks -> conflict-free.

#define GP 36                    // smem pitch (floats)
#define GTILE (128 * GP)         // one buffer (floats)
#define GSMEM_BYTES (4 * GTILE * 4)  // A0,A1,B0,B1

__device__ __forceinline__ unsigned f2tf32(float f) {
    unsigned u;
    asm("cvt.rna.tf32.f32 %0, %1;" : "=r"(u) : "f"(f));
    return u;
}

__device__ __forceinline__ void cp16(float* s, const float* g) {
    unsigned sa = (unsigned)__cvta_generic_to_shared(s);
    asm volatile("cp.async.cg.shared.global [%0], [%1], 16;" :: "r"(sa), "l"(g));
}

__device__ __forceinline__ void mma_tf32(
    float& d0, float& d1, float& d2, float& d3,
    unsigned a0, unsigned a1, unsigned a2, unsigned a3,
    unsigned b0, unsigned b1)
{
    asm volatile(
        "mma.sync.aligned.m16n8k8.row.col.f32.tf32.tf32.f32 "
        "{%0,%1,%2,%3}, {%4,%5,%6,%7}, {%8,%9}, {%0,%1,%2,%3};"
        : "+f"(d0), "+f"(d1), "+f"(d2), "+f"(d3)
        : "r"(a0), "r"(a1), "r"(a2), "r"(a3), "r"(b0), "r"(b1));
}

template<bool RELU, bool RES>
__global__ void __launch_bounds__(256, 2) gemm_kernel(
    const float* __restrict__ A, const float* __restrict__ W,
    const float* __restrict__ bias, const float* __restrict__ R,
    float* __restrict__ C, int M, int N, int K)
{
    extern __shared__ float sm[];
    float* Abuf[2] = { sm,             sm + GTILE };
    float* Bbuf[2] = { sm + 2*GTILE,   sm + 3*GTILE };

    const int m0 = blockIdx.y * 128, n0 = blockIdx.x * 128;
    const int tid  = threadIdx.x;
    const int lane = tid & 31;
    const int warp = tid >> 5;
    const int wm = warp >> 2;        // 0..1  -> 64 rows
    const int wn = warp & 3;         // 0..3  -> 32 cols

    // global->smem mapping: 1024 float4 per tile, 4 per thread
    int ld_row[4], ld_c4[4];
    #pragma unroll
    for (int l = 0; l < 4; l++) {
        int idx = tid + l * 256;
        ld_row[l] = idx >> 3;
        ld_c4[l]  = (idx & 7) << 2;
    }

    const int KT = K >> 5;           // K / 32

    // prologue: tile 0
    #pragma unroll
    for (int l = 0; l < 4; l++) {
        cp16(Abuf[0] + ld_row[l]*GP + ld_c4[l], A + (size_t)(m0 + ld_row[l])*K + ld_c4[l]);
        cp16(Bbuf[0] + ld_row[l]*GP + ld_c4[l], W + (size_t)(n0 + ld_row[l])*K + ld_c4[l]);
    }
    asm volatile("cp.async.commit_group;");

    float acc[4][4][4] = {};
    const int lr = lane >> 2;        // 0..7
    const int lc = lane & 3;         // 0..3

    for (int kt = 0; kt < KT; kt++) {
        if (kt + 1 < KT) {
            const int k0 = (kt + 1) << 5;
            float* An = Abuf[(kt + 1) & 1];
            float* Bn = Bbuf[(kt + 1) & 1];
            #pragma unroll
            for (int l = 0; l < 4; l++) {
                cp16(An + ld_row[l]*GP + ld_c4[l], A + (size_t)(m0 + ld_row[l])*K + k0 + ld_c4[l]);
                cp16(Bn + ld_row[l]*GP + ld_c4[l], W + (size_t)(n0 + ld_row[l])*K + k0 + ld_c4[l]);
            }
            asm volatile("cp.async.commit_group;");
            asm volatile("cp.async.wait_group 1;");
        } else {
            asm volatile("cp.async.wait_group 0;");
        }
        __syncthreads();

        const float* At = Abuf[kt & 1] + (wm*64 + lr) * GP;
        const float* Bt = Bbuf[kt & 1] + (wn*32 + lr) * GP;

        #pragma unroll
        for (int ks = 0; ks < 4; ks++) {
            const int kk = ks*8 + lc;
            unsigned af[4][4], bf[4][2];
            #pragma unroll
            for (int i = 0; i < 4; i++) {
                const float* p = At + i*16*GP;
                af[i][0] = f2tf32(p[kk]);
                af[i][1] = f2tf32(p[8*GP + kk]);
                af[i][2] = f2tf32(p[kk + 4]);
                af[i][3] = f2tf32(p[8*GP + kk + 4]);
            }
            #pragma unroll
            for (int j = 0; j < 4; j++) {
                const float* p = Bt + j*8*GP;
                bf[j][0] = f2tf32(p[kk]);
                bf[j][1] = f2tf32(p[kk + 4]);
            }
            #pragma unroll
            for (int i = 0; i < 4; i++)
                #pragma unroll
                for (int j = 0; j < 4; j++)
                    mma_tf32(acc[i][j][0], acc[i][j][1], acc[i][j][2], acc[i][j][3],
                             af[i][0], af[i][1], af[i][2], af[i][3],
                             bf[j][0], bf[j][1]);
        }
        __syncthreads();
    }

    // epilogue: c0,c1 at (row, col..col+1), c2,c3 at (row+8, ...)
    #pragma unroll
    for (int i = 0; i < 4; i++) {
        const int m = m0 + wm*64 + i*16 + lr;
        #pragma unroll
        for (int j = 0; j < 4; j++) {
            const int n = n0 + wn*32 + j*8 + lc*2;
            const float bx = bias[n], by = bias[n + 1];
            float v0 = acc[i][j][0] + bx, v1 = acc[i][j][1] + by;
            float v2 = acc[i][j][2] + bx, v3 = acc[i][j][3] + by;
            if (RELU) {
                v0 = fmaxf(v0, 0.f); v1 = fmaxf(v1, 0.f);
                v2 = fmaxf(v2, 0.f); v3 = fmaxf(v3, 0.f);
            }
            if (RES) {
                float2 r0 = *(const float2*)(R + (size_t)m*N + n);
                float2 r1 = *(const float2*)(R + (size_t)(m+8)*N + n);
                v0 += r0.x; v1 += r0.y; v2 += r1.x; v3 += r1.y;
            }
            *(float2*)(C + (size_t)m*N + n)     = make_float2(v0, v1);
            *(float2*)(C + (size_t)(m+8)*N + n) = make_float2(v2, v3);
        }
    }
}

// ---------------- flash attention: one CTA per (b, h, 64-query tile) --------
#define FL_SMEM_FLOATS (64*64 + 3*64*65 + 3*64 + 64)
#define FL_SMEM_BYTES  (FL_SMEM_FLOATS * 4)

__global__ void __launch_bounds__(256) flash_kernel(
    const float* __restrict__ Q, const float* __restrict__ K,
    const float* __restrict__ V, const int* __restrict__ mask,
    float* __restrict__ O)
{
    const int qt = blockIdx.x, h = blockIdx.y, b = blockIdx.z;
    const int tid = threadIdx.x;
    const int tx = tid & 15, ty = tid >> 4;
    extern __shared__ float sm[];
    float* Qs   = sm;                 // [64][64]
    float* Ks   = Qs + 64 * 64;       // [64][65]
    float* Vs   = Ks + 64 * 65;       // [64][65]
    float* Ps   = Vs + 64 * 65;       // [64][65]
    float* mrow = Ps + 64 * 65;       // [64]
    float* lrow = mrow + 64;
    float* srow = lrow + 64;
    int*   mkf  = (int*)(srow + 64);

    const int q0 = qt * 64;
    const size_t rb = (size_t)b * SEQ;

    #pragma unroll
    for (int l = 0; l < 4; l++) {
        int idx = tid + l * 256;
        int r = idx >> 4, c4 = (idx & 15) << 2;
        float4 qv = *(const float4*)(Q + (rb + q0 + r) * D_MODEL + h * DK + c4);
        Qs[r * 64 + c4 + 0] = qv.x; Qs[r * 64 + c4 + 1] = qv.y;
        Qs[r * 64 + c4 + 2] = qv.z; Qs[r * 64 + c4 + 3] = qv.w;
    }
    if (tid < 64) { mrow[tid] = -1e30f; lrow[tid] = 0.f; }

    float acc[4][4] = {};

    for (int kt = 0; kt < SEQ / 64; kt++) {
        const int k0 = kt * 64;
        __syncthreads();
        #pragma unroll
        for (int l = 0; l < 4; l++) {
            int idx = tid + l * 256;
            int r = idx >> 4, c4 = (idx & 15) << 2;
            float4 kv = *(const float4*)(K + (rb + k0 + r) * D_MODEL + h * DK + c4);
            Ks[r * 65 + c4 + 0] = kv.x; Ks[r * 65 + c4 + 1] = kv.y;
            Ks[r * 65 + c4 + 2] = kv.z; Ks[r * 65 + c4 + 3] = kv.w;
            float4 vv = *(const float4*)(V + (rb + k0 + r) * D_MODEL + h * DK + c4);
            Vs[r * 65 + c4 + 0] = vv.x; Vs[r * 65 + c4 + 1] = vv.y;
            Vs[r * 65 + c4 + 2] = vv.z; Vs[r * 65 + c4 + 3] = vv.w;
        }
        if (tid < 64) mkf[tid] = mask[b * SEQ + k0 + tid];
        __syncthreads();

        float s[4][4] = {};
        #pragma unroll 16
        for (int kk = 0; kk < 64; kk++) {
            float qr[4], kr[4];
            #pragma unroll
            for (int i = 0; i < 4; i++) qr[i] = Qs[(ty * 4 + i) * 64 + kk];
            #pragma unroll
            for (int j = 0; j < 4; j++) kr[j] = Ks[(tx * 4 + j) * 65 + kk];
            #pragma unroll
            for (int i = 0; i < 4; i++)
                #pragma unroll
                for (int j = 0; j < 4; j++)
                    s[i][j] += qr[i] * kr[j];
        }
        #pragma unroll
        for (int i = 0; i < 4; i++)
            #pragma unroll
            for (int j = 0; j < 4; j++) {
                float val = s[i][j] * 0.125f;
                if (mkf[tx * 4 + j] == 1) val = -1e30f;
                Ps[(ty * 4 + i) * 65 + tx * 4 + j] = val;
            }
        __syncthreads();

        {
            const int q = tid >> 2, sg = tid & 3;
            const float m_old = mrow[q];
            float mx = m_old;
            #pragma unroll
            for (int jj = 0; jj < 16; jj++)
                mx = fmaxf(mx, Ps[q * 65 + sg * 16 + jj]);
            mx = fmaxf(mx, __shfl_xor_sync(0xffffffffu, mx, 1));
            mx = fmaxf(mx, __shfl_xor_sync(0xffffffffu, mx, 2));
            float sum = 0.f;
            #pragma unroll
            for (int jj = 0; jj < 16; jj++) {
                float p = __expf(Ps[q * 65 + sg * 16 + jj] - mx);
                Ps[q * 65 + sg * 16 + jj] = p;
                sum += p;
            }
            sum += __shfl_xor_sync(0xffffffffu, sum, 1);
            sum += __shfl_xor_sync(0xffffffffu, sum, 2);
            if (sg == 0) {
                float corr = __expf(m_old - mx);
                lrow[q] = lrow[q] * corr + sum;
                mrow[q] = mx;
                srow[q] = corr;
            }
        }
        __syncthreads();

        float sc[4];
        #pragma unroll
        for (int i = 0; i < 4; i++) sc[i] = srow[ty * 4 + i];
        #pragma unroll
        for (int i = 0; i < 4; i++)
            #pragma unroll
            for (int d = 0; d < 4; d++) acc[i][d] *= sc[i];
        #pragma unroll 8
        for (int j = 0; j < 64; j++) {
            float pr[4], vr[4];
            #pragma unroll
            for (int i = 0; i < 4; i++) pr[i] = Ps[(ty * 4 + i) * 65 + j];
            #pragma unroll
            for (int d = 0; d < 4; d++) vr[d] = Vs[j * 65 + tx * 4 + d];
            #pragma unroll
            for (int i = 0; i < 4; i++)
                #pragma unroll
                for (int d = 0; d < 4; d++)
                    acc[i][d] += pr[i] * vr[d];
        }
    }

    #pragma unroll
    for (int i = 0; i < 4; i++) {
        const float inv = 1.0f / lrow[ty * 4 + i];
        float4 o;
        o.x = acc[i][0] * inv; o.y = acc[i][1] * inv;
        o.z = acc[i][2] * inv; o.w = acc[i][3] * inv;
        *(float4*)(O + (rb + q0 + ty * 4 + i) * D_MODEL + h * DK + tx * 4) = o;
    }
}

// ---------------- orchestration ---------------------------------------------
extern "C" void kernel_launch(void* const* d_in, const int* in_sizes, int n_in,
                              void* d_out, int out_size)
{
    const float* x      = (const float*)d_in[0];
    const int*   mask   = (const int*)  d_in[1];
    const float* alpha1 = (const float*)d_in[2];
    const float* bias1  = (const float*)d_in[3];
    const float* alpha2 = (const float*)d_in[4];
    const float* bias2  = (const float*)d_in[5];
    const float* Wq = (const float*)d_in[6];   const float* bq = (const float*)d_in[7];
    const float* Wk = (const float*)d_in[8];   const float* bk = (const float*)d_in[9];
    const float* Wv = (const float*)d_in[10];  const float* bv = (const float*)d_in[11];
    const float* Wo = (const float*)d_in[12];  const float* bo = (const float*)d_in[13];
    const float* W1 = (const float*)d_in[14];  const float* b1 = (const float*)d_in[15];
    const float* W2 = (const float*)d_in[16];  const float* b2 = (const float*)d_in[17];
    float* out = (float*)d_out;

    float *x2, *q, *k, *v, *attn, *xres, *hbuf;
    cudaGetSymbolAddress((void**)&x2,   g_x2);
    cudaGetSymbolAddress((void**)&q,    g_q);
    cudaGetSymbolAddress((void**)&k,    g_k);
    cudaGetSymbolAddress((void**)&v,    g_v);
    cudaGetSymbolAddress((void**)&attn, g_attn);
    cudaGetSymbolAddress((void**)&xres, g_xres);
    cudaGetSymbolAddress((void**)&hbuf, g_h);

    cudaFuncSetAttribute(flash_kernel,
                         cudaFuncAttributeMaxDynamicSharedMemorySize, FL_SMEM_BYTES);
    cudaFuncSetAttribute(gemm_kernel<false, false>,
                         cudaFuncAttributeMaxDynamicSharedMemorySize, GSMEM_BYTES);
    cudaFuncSetAttribute(gemm_kernel<false, true>,
                         cudaFuncAttributeMaxDynamicSharedMemorySize, GSMEM_BYTES);
    cudaFuncSetAttribute(gemm_kernel<true, false>,
                         cudaFuncAttributeMaxDynamicSharedMemorySize, GSMEM_BYTES);

    const dim3 gProj(D_MODEL / 128, ROWS / 128);   // (8, 64)
    const dim3 gFF1 (D_FF    / 128, ROWS / 128);   // (16, 64)

    norm_kernel<<<ROWS, 256>>>(x, alpha1, bias1, x2);
    gemm_kernel<false, false><<<gProj, 256, GSMEM_BYTES>>>(x2, Wq, bq, nullptr, q, ROWS, D_MODEL, D_MODEL);
    gemm_kernel<false, false><<<gProj, 256, GSMEM_BYTES>>>(x2, Wk, bk, nullptr, k, ROWS, D_MODEL, D_MODEL);
    gemm_kernel<false, false><<<gProj, 256, GSMEM_BYTES>>>(x2, Wv, bv, nullptr, v, ROWS, D_MODEL, D_MODEL);
    flash_kernel<<<dim3(SEQ / 64, HEADS, BATCH), 256, FL_SMEM_BYTES>>>(q, k, v, mask, attn);
    gemm_kernel<false, true ><<<gProj, 256, GSMEM_BYTES>>>(attn, Wo, bo, x, xres, ROWS, D_MODEL, D_MODEL);
    norm_kernel<<<ROWS, 256>>>(xres, alpha2, bias2, x2);
    gemm_kernel<true,  false><<<gFF1, 256, GSMEM_BYTES>>>(x2, W1, b1, nullptr, hbuf, ROWS, D_FF, D_MODEL);
    gemm_kernel<false, true ><<<gProj, 256, GSMEM_BYTES>>>(hbuf, W2, b2, xres, out, ROWS, D_MODEL, D_FF);
}

// round 3
// speedup vs baseline: 3.4007x; 1.9309x over previous
#include <cuda_runtime.h>
#include <math.h>

#define D_MODEL 1024
#define D_FF    2048
#define BATCH   4
#define SEQ     2048
#define HEADS   16
#define DK      64
#define ROWS    (BATCH * SEQ)   // 8192

// ---------------- scratch (no allocs allowed -> __device__ globals) ----------
__device__ float g_x2  [ROWS * D_MODEL];
__device__ float g_q   [ROWS * D_MODEL];
__device__ float g_k   [ROWS * D_MODEL];
__device__ float g_v   [ROWS * D_MODEL];
__device__ float g_attn[ROWS * D_MODEL];
__device__ float g_xres[ROWS * D_MODEL];
__device__ float g_h   [ROWS * D_FF];

// ---------------- common helpers --------------------------------------------
__device__ __forceinline__ unsigned f2tf32(float f) {
    unsigned u;
    asm("cvt.rna.tf32.f32 %0, %1;" : "=r"(u) : "f"(f));
    return u;
}

__device__ __forceinline__ void cp16(float* s, const float* g) {
    unsigned sa = (unsigned)__cvta_generic_to_shared(s);
    asm volatile("cp.async.cg.shared.global [%0], [%1], 16;" :: "r"(sa), "l"(g));
}

__device__ __forceinline__ void mma_tf32(
    float& d0, float& d1, float& d2, float& d3,
    unsigned a0, unsigned a1, unsigned a2, unsigned a3,
    unsigned b0, unsigned b1)
{
    asm volatile(
        "mma.sync.aligned.m16n8k8.row.col.f32.tf32.tf32.f32 "
        "{%0,%1,%2,%3}, {%4,%5,%6,%7}, {%8,%9}, {%0,%1,%2,%3};"
        : "+f"(d0), "+f"(d1), "+f"(d2), "+f"(d3)
        : "r"(a0), "r"(a1), "r"(a2), "r"(a3), "r"(b0), "r"(b1));
}

// ---------------- LayerNorm: alpha*(x-mu)/(std+eps)+bias, std unbiased ------
__global__ void __launch_bounds__(256) norm_kernel(
    const float* __restrict__ x, const float* __restrict__ alpha,
    const float* __restrict__ bias, float* __restrict__ out)
{
    const int row = blockIdx.x;
    const int t = threadIdx.x;
    const float4* xr = (const float4*)(x + (size_t)row * D_MODEL);
    float4 v = xr[t];
    float s  = v.x + v.y + v.z + v.w;
    float ss = v.x*v.x + v.y*v.y + v.z*v.z + v.w*v.w;
    #pragma unroll
    for (int o = 16; o; o >>= 1) {
        s  += __shfl_xor_sync(0xffffffffu, s, o);
        ss += __shfl_xor_sync(0xffffffffu, ss, o);
    }
    __shared__ float rs[8], rss[8];
    __shared__ float s_mu, s_inv;
    const int w = t >> 5, l = t & 31;
    if (l == 0) { rs[w] = s; rss[w] = ss; }
    __syncthreads();
    if (t == 0) {
        float S = 0.f, SS = 0.f;
        #pragma unroll
        for (int i = 0; i < 8; i++) { S += rs[i]; SS += rss[i]; }
        float mu  = S * (1.0f / D_MODEL);
        float var = (SS - (float)D_MODEL * mu * mu) * (1.0f / (D_MODEL - 1));
        s_mu  = mu;
        s_inv = 1.0f / (sqrtf(fmaxf(var, 0.f)) + 1e-6f);
    }
    __syncthreads();
    const float mu = s_mu, inv = s_inv;
    float4 av = ((const float4*)alpha)[t];
    float4 bv = ((const float4*)bias)[t];
    float4 o;
    o.x = av.x * (v.x - mu) * inv + bv.x;
    o.y = av.y * (v.y - mu) * inv + bv.y;
    o.z = av.z * (v.z - mu) * inv + bv.z;
    o.w = av.w * (v.w - mu) * inv + bv.w;
    ((float4*)(out + (size_t)row * D_MODEL))[t] = o;
}

// ---------------- tf32 tensor-core GEMM --------------------------------------
#define GP 36
#define GTILE (128 * GP)
#define GSMEM_BYTES (4 * GTILE * 4)

template<bool RELU, bool RES>
__global__ void __launch_bounds__(256, 2) gemm_kernel(
    const float* __restrict__ A, const float* __restrict__ W,
    const float* __restrict__ bias, const float* __restrict__ R,
    float* __restrict__ C, int M, int N, int K)
{
    extern __shared__ float sm[];
    float* Abuf[2] = { sm,             sm + GTILE };
    float* Bbuf[2] = { sm + 2*GTILE,   sm + 3*GTILE };

    const int m0 = blockIdx.y * 128, n0 = blockIdx.x * 128;
    const int tid  = threadIdx.x;
    const int lane = tid & 31;
    const int warp = tid >> 5;
    const int wm = warp >> 2;
    const int wn = warp & 3;

    int ld_row[4], ld_c4[4];
    #pragma unroll
    for (int l = 0; l < 4; l++) {
        int idx = tid + l * 256;
        ld_row[l] = idx >> 3;
        ld_c4[l]  = (idx & 7) << 2;
    }

    const int KT = K >> 5;

    #pragma unroll
    for (int l = 0; l < 4; l++) {
        cp16(Abuf[0] + ld_row[l]*GP + ld_c4[l], A + (size_t)(m0 + ld_row[l])*K + ld_c4[l]);
        cp16(Bbuf[0] + ld_row[l]*GP + ld_c4[l], W + (size_t)(n0 + ld_row[l])*K + ld_c4[l]);
    }
    asm volatile("cp.async.commit_group;");

    float acc[4][4][4] = {};
    const int lr = lane >> 2;
    const int lc = lane & 3;

    for (int kt = 0; kt < KT; kt++) {
        if (kt + 1 < KT) {
            const int k0 = (kt + 1) << 5;
            float* An = Abuf[(kt + 1) & 1];
            float* Bn = Bbuf[(kt + 1) & 1];
            #pragma unroll
            for (int l = 0; l < 4; l++) {
                cp16(An + ld_row[l]*GP + ld_c4[l], A + (size_t)(m0 + ld_row[l])*K + k0 + ld_c4[l]);
                cp16(Bn + ld_row[l]*GP + ld_c4[l], W + (size_t)(n0 + ld_row[l])*K + k0 + ld_c4[l]);
            }
            asm volatile("cp.async.commit_group;");
            asm volatile("cp.async.wait_group 1;");
        } else {
            asm volatile("cp.async.wait_group 0;");
        }
        __syncthreads();

        const float* At = Abuf[kt & 1] + (wm*64 + lr) * GP;
        const float* Bt = Bbuf[kt & 1] + (wn*32 + lr) * GP;

        #pragma unroll
        for (int ks = 0; ks < 4; ks++) {
            const int kk = ks*8 + lc;
            unsigned af[4][4], bf[4][2];
            #pragma unroll
            for (int i = 0; i < 4; i++) {
                const float* p = At + i*16*GP;
                af[i][0] = f2tf32(p[kk]);
                af[i][1] = f2tf32(p[8*GP + kk]);
                af[i][2] = f2tf32(p[kk + 4]);
                af[i][3] = f2tf32(p[8*GP + kk + 4]);
            }
            #pragma unroll
            for (int j = 0; j < 4; j++) {
                const float* p = Bt + j*8*GP;
                bf[j][0] = f2tf32(p[kk]);
                bf[j][1] = f2tf32(p[kk + 4]);
            }
            #pragma unroll
            for (int i = 0; i < 4; i++)
                #pragma unroll
                for (int j = 0; j < 4; j++)
                    mma_tf32(acc[i][j][0], acc[i][j][1], acc[i][j][2], acc[i][j][3],
                             af[i][0], af[i][1], af[i][2], af[i][3],
                             bf[j][0], bf[j][1]);
        }
        __syncthreads();
    }

    #pragma unroll
    for (int i = 0; i < 4; i++) {
        const int m = m0 + wm*64 + i*16 + lr;
        #pragma unroll
        for (int j = 0; j < 4; j++) {
            const int n = n0 + wn*32 + j*8 + lc*2;
            const float bx = bias[n], by = bias[n + 1];
            float v0 = acc[i][j][0] + bx, v1 = acc[i][j][1] + by;
            float v2 = acc[i][j][2] + bx, v3 = acc[i][j][3] + by;
            if (RELU) {
                v0 = fmaxf(v0, 0.f); v1 = fmaxf(v1, 0.f);
                v2 = fmaxf(v2, 0.f); v3 = fmaxf(v3, 0.f);
            }
            if (RES) {
                float2 r0 = *(const float2*)(R + (size_t)m*N + n);
                float2 r1 = *(const float2*)(R + (size_t)(m+8)*N + n);
                v0 += r0.x; v1 += r0.y; v2 += r1.x; v3 += r1.y;
            }
            *(float2*)(C + (size_t)m*N + n)     = make_float2(v0, v1);
            *(float2*)(C + (size_t)(m+8)*N + n) = make_float2(v2, v3);
        }
    }
}

// ---------------- tensor-core flash attention --------------------------------
// CTA: 128 queries (8 warps x m16), 64-key tiles, DK=64, tf32 mma m16n8k8.
// K smem pitch 68, V pitch 72 -> conflict-free fragment reads.
#define BQ 128
#define BK 64
#define KP 68
#define VP 72
#define FL_NT (SEQ / BK)
#define FL_K_OFF 0
#define FL_V_OFF (2 * 64 * KP)
#define FL_M_OFF (FL_V_OFF + 2 * 64 * VP)
#define FL_SMEM_BYTES ((FL_M_OFF + 2 * 64) * 4)

__global__ void __launch_bounds__(256, 1) flash_kernel(
    const float* __restrict__ Q, const float* __restrict__ Kg,
    const float* __restrict__ Vg, const int* __restrict__ mask,
    float* __restrict__ O)
{
    extern __shared__ unsigned smu[];
    unsigned* KsA = smu + FL_K_OFF;
    unsigned* VsA = smu + FL_V_OFF;
    float*    mbA = (float*)(smu + FL_M_OFF);

    const int qt = blockIdx.x, h = blockIdx.y, b = blockIdx.z;
    const int tid = threadIdx.x, lane = tid & 31, warp = tid >> 5;
    const int q = lane & 3, r = lane >> 2;
    const size_t rb = (size_t)b * SEQ;
    const int hb = h * DK;
    const int q0 = qt * BQ;

    // Q fragments, pre-scaled by 1/sqrt(dk)=0.125
    unsigned qf[8][4];
    {
        const float* QA = Q + (rb + q0 + warp*16 + r) * D_MODEL + hb;
        const float* QB = QA + 8 * D_MODEL;
        #pragma unroll
        for (int ks = 0; ks < 8; ks++) {
            const int c = ks*8 + q;
            qf[ks][0] = f2tf32(0.125f * QA[c]);
            qf[ks][1] = f2tf32(0.125f * QB[c]);
            qf[ks][2] = f2tf32(0.125f * QA[c + 4]);
            qf[ks][3] = f2tf32(0.125f * QB[c + 4]);
        }
    }

    // staging map: 1024 float4 per 64x64 tile, 4 per thread
    int srow[4], sc4[4];
    #pragma unroll
    for (int l = 0; l < 4; l++) {
        int idx = tid + l * 256;
        srow[l] = idx >> 4;
        sc4[l]  = (idx & 15) << 2;
    }

    float4 kreg[4], vreg[4];
    float mbias = 0.f;
    #pragma unroll
    for (int l = 0; l < 4; l++) {
        kreg[l] = *(const float4*)(Kg + (rb + srow[l]) * D_MODEL + hb + sc4[l]);
        vreg[l] = *(const float4*)(Vg + (rb + srow[l]) * D_MODEL + hb + sc4[l]);
    }
    if (tid < 64) mbias = (mask[b * SEQ + tid] == 1) ? -1e30f : 0.f;
    #pragma unroll
    for (int l = 0; l < 4; l++) {
        uint4 kw, vw;
        kw.x = f2tf32(kreg[l].x); kw.y = f2tf32(kreg[l].y);
        kw.z = f2tf32(kreg[l].z); kw.w = f2tf32(kreg[l].w);
        vw.x = f2tf32(vreg[l].x); vw.y = f2tf32(vreg[l].y);
        vw.z = f2tf32(vreg[l].z); vw.w = f2tf32(vreg[l].w);
        *(uint4*)&KsA[srow[l]*KP + sc4[l]] = kw;
        *(uint4*)&VsA[srow[l]*VP + sc4[l]] = vw;
    }
    if (tid < 64) mbA[tid] = mbias;
    __syncthreads();

    float oacc[8][4] = {};
    float m0 = -1e30f, m1 = -1e30f, l0 = 0.f, l1 = 0.f;

    for (int kt = 0; kt < FL_NT; kt++) {
        const int cur = kt & 1, nxt = cur ^ 1;

        // prefetch next tile into registers (latency hidden by compute)
        if (kt + 1 < FL_NT) {
            const int k0n = (kt + 1) * BK;
            #pragma unroll
            for (int l = 0; l < 4; l++) {
                kreg[l] = *(const float4*)(Kg + (rb + k0n + srow[l]) * D_MODEL + hb + sc4[l]);
                vreg[l] = *(const float4*)(Vg + (rb + k0n + srow[l]) * D_MODEL + hb + sc4[l]);
            }
            if (tid < 64) mbias = (mask[b * SEQ + k0n + tid] == 1) ? -1e30f : 0.f;
        }

        const unsigned* Kc = KsA + cur * 64 * KP;
        const unsigned* Vc = VsA + cur * 64 * VP;
        const float*    mc = mbA + cur * 64;

        // S = (Q/8) @ K^T
        float sa[8][4] = {};
        #pragma unroll
        for (int nb = 0; nb < 8; nb++) {
            const unsigned* Kr = Kc + (nb*8 + r) * KP + q;
            #pragma unroll
            for (int ks = 0; ks < 8; ks++) {
                unsigned b0 = Kr[ks*8];
                unsigned b1 = Kr[ks*8 + 4];
                mma_tf32(sa[nb][0], sa[nb][1], sa[nb][2], sa[nb][3],
                         qf[ks][0], qf[ks][1], qf[ks][2], qf[ks][3], b0, b1);
            }
        }

        // mask bias + row max
        float mx0 = m0, mx1 = m1;
        #pragma unroll
        for (int nb = 0; nb < 8; nb++) {
            float2 bb = *(const float2*)&mc[nb*8 + 2*q];
            sa[nb][0] += bb.x; sa[nb][1] += bb.y;
            sa[nb][2] += bb.x; sa[nb][3] += bb.y;
            mx0 = fmaxf(mx0, fmaxf(sa[nb][0], sa[nb][1]));
            mx1 = fmaxf(mx1, fmaxf(sa[nb][2], sa[nb][3]));
        }
        mx0 = fmaxf(mx0, __shfl_xor_sync(0xffffffffu, mx0, 1));
        mx0 = fmaxf(mx0, __shfl_xor_sync(0xffffffffu, mx0, 2));
        mx1 = fmaxf(mx1, __shfl_xor_sync(0xffffffffu, mx1, 1));
        mx1 = fmaxf(mx1, __shfl_xor_sync(0xffffffffu, mx1, 2));

        const float corr0 = __expf(m0 - mx0);
        const float corr1 = __expf(m1 - mx1);
        float sum0 = 0.f, sum1 = 0.f;
        #pragma unroll
        for (int nb = 0; nb < 8; nb++) {
            sa[nb][0] = __expf(sa[nb][0] - mx0);
            sa[nb][1] = __expf(sa[nb][1] - mx0);
            sa[nb][2] = __expf(sa[nb][2] - mx1);
            sa[nb][3] = __expf(sa[nb][3] - mx1);
            sum0 += sa[nb][0] + sa[nb][1];
            sum1 += sa[nb][2] + sa[nb][3];
        }
        sum0 += __shfl_xor_sync(0xffffffffu, sum0, 1);
        sum0 += __shfl_xor_sync(0xffffffffu, sum0, 2);
        sum1 += __shfl_xor_sync(0xffffffffu, sum1, 1);
        sum1 += __shfl_xor_sync(0xffffffffu, sum1, 2);
        l0 = l0 * corr0 + sum0; m0 = mx0;
        l1 = l1 * corr1 + sum1; m1 = mx1;

        #pragma unroll
        for (int d = 0; d < 8; d++) {
            oacc[d][0] *= corr0; oacc[d][1] *= corr0;
            oacc[d][2] *= corr1; oacc[d][3] *= corr1;
        }

        // P @ V : rearrange S (C layout) -> A layout via quad butterfly
        const int src0 = (lane & ~3) | (q >> 1);
        const int src1 = src0 + 2;
        const bool od = (q & 1);
        #pragma unroll
        for (int j = 0; j < 8; j++) {
            float t00 = __shfl_sync(0xffffffffu, sa[j][0], src0);
            float t01 = __shfl_sync(0xffffffffu, sa[j][1], src0);
            float t20 = __shfl_sync(0xffffffffu, sa[j][2], src0);
            float t21 = __shfl_sync(0xffffffffu, sa[j][3], src0);
            float t40 = __shfl_sync(0xffffffffu, sa[j][0], src1);
            float t41 = __shfl_sync(0xffffffffu, sa[j][1], src1);
            float t60 = __shfl_sync(0xffffffffu, sa[j][2], src1);
            float t61 = __shfl_sync(0xffffffffu, sa[j][3], src1);
            unsigned pa0 = f2tf32(od ? t01 : t00);
            unsigned pa1 = f2tf32(od ? t21 : t20);
            unsigned pa2 = f2tf32(od ? t41 : t40);
            unsigned pa3 = f2tf32(od ? t61 : t60);
            const unsigned* Vr = Vc + (j*8 + q) * VP + r;
            #pragma unroll
            for (int d = 0; d < 8; d++) {
                unsigned vb0 = Vr[d*8];
                unsigned vb1 = Vr[4*VP + d*8];
                mma_tf32(oacc[d][0], oacc[d][1], oacc[d][2], oacc[d][3],
                         pa0, pa1, pa2, pa3, vb0, vb1);
            }
        }

        __syncthreads();
        if (kt + 1 < FL_NT) {
            unsigned* Kn = KsA + nxt * 64 * KP;
            unsigned* Vn = VsA + nxt * 64 * VP;
            #pragma unroll
            for (int l = 0; l < 4; l++) {
                uint4 kw, vw;
                kw.x = f2tf32(kreg[l].x); kw.y = f2tf32(kreg[l].y);
                kw.z = f2tf32(kreg[l].z); kw.w = f2tf32(kreg[l].w);
                vw.x = f2tf32(vreg[l].x); vw.y = f2tf32(vreg[l].y);
                vw.z = f2tf32(vreg[l].z); vw.w = f2tf32(vreg[l].w);
                *(uint4*)&Kn[srow[l]*KP + sc4[l]] = kw;
                *(uint4*)&Vn[srow[l]*VP + sc4[l]] = vw;
            }
            if (tid < 64) mbA[nxt * 64 + tid] = mbias;
        }
        __syncthreads();
    }

    // epilogue
    const float inv0 = 1.0f / l0, inv1 = 1.0f / l1;
    const int rowA = q0 + warp*16 + r;
    float* OA = O + (rb + rowA) * D_MODEL + hb;
    float* OB = OA + 8 * D_MODEL;
    #pragma unroll
    for (int d = 0; d < 8; d++) {
        *(float2*)(OA + d*8 + 2*q) = make_float2(oacc[d][0] * inv0, oacc[d][1] * inv0);
        *(float2*)(OB + d*8 + 2*q) = make_float2(oacc[d][2] * inv1, oacc[d][3] * inv1);
    }
}

// ---------------- orchestration ---------------------------------------------
extern "C" void kernel_launch(void* const* d_in, const int* in_sizes, int n_in,
                              void* d_out, int out_size)
{
    const float* x      = (const float*)d_in[0];
    const int*   mask   = (const int*)  d_in[1];
    const float* alpha1 = (const float*)d_in[2];
    const float* bias1  = (const float*)d_in[3];
    const float* alpha2 = (const float*)d_in[4];
    const float* bias2  = (const float*)d_in[5];
    const float* Wq = (const float*)d_in[6];   const float* bq = (const float*)d_in[7];
    const float* Wk = (const float*)d_in[8];   const float* bk = (const float*)d_in[9];
    const float* Wv = (const float*)d_in[10];  const float* bv = (const float*)d_in[11];
    const float* Wo = (const float*)d_in[12];  const float* bo = (const float*)d_in[13];
    const float* W1 = (const float*)d_in[14];  const float* b1 = (const float*)d_in[15];
    const float* W2 = (const float*)d_in[16];  const float* b2 = (const float*)d_in[17];
    float* out = (float*)d_out;

    float *x2, *q, *k, *v, *attn, *xres, *hbuf;
    cudaGetSymbolAddress((void**)&x2,   g_x2);
    cudaGetSymbolAddress((void**)&q,    g_q);
    cudaGetSymbolAddress((void**)&k,    g_k);
    cudaGetSymbolAddress((void**)&v,    g_v);
    cudaGetSymbolAddress((void**)&attn, g_attn);
    cudaGetSymbolAddress((void**)&xres, g_xres);
    cudaGetSymbolAddress((void**)&hbuf, g_h);

    cudaFuncSetAttribute(flash_kernel,
                         cudaFuncAttributeMaxDynamicSharedMemorySize, FL_SMEM_BYTES);
    cudaFuncSetAttribute(gemm_kernel<false, false>,
                         cudaFuncAttributeMaxDynamicSharedMemorySize, GSMEM_BYTES);
    cudaFuncSetAttribute(gemm_kernel<false, true>,
                         cudaFuncAttributeMaxDynamicSharedMemorySize, GSMEM_BYTES);
    cudaFuncSetAttribute(gemm_kernel<true, false>,
                         cudaFuncAttributeMaxDynamicSharedMemorySize, GSMEM_BYTES);

    const dim3 gProj(D_MODEL / 128, ROWS / 128);
    const dim3 gFF1 (D_FF    / 128, ROWS / 128);

    norm_kernel<<<ROWS, 256>>>(x, alpha1, bias1, x2);
    gemm_kernel<false, false><<<gProj, 256, GSMEM_BYTES>>>(x2, Wq, bq, nullptr, q, ROWS, D_MODEL, D_MODEL);
    gemm_kernel<false, false><<<gProj, 256, GSMEM_BYTES>>>(x2, Wk, bk, nullptr, k, ROWS, D_MODEL, D_MODEL);
    gemm_kernel<false, false><<<gProj, 256, GSMEM_BYTES>>>(x2, Wv, bv, nullptr, v, ROWS, D_MODEL, D_MODEL);
    flash_kernel<<<dim3(SEQ / BQ, HEADS, BATCH), 256, FL_SMEM_BYTES>>>(q, k, v, mask, attn);
    gemm_kernel<false, true ><<<gProj, 256, GSMEM_BYTES>>>(attn, Wo, bo, x, xres, ROWS, D_MODEL, D_MODEL);
    norm_kernel<<<ROWS, 256>>>(xres, alpha2, bias2, x2);
    gemm_kernel<true,  false><<<gFF1, 256, GSMEM_BYTES>>>(x2, W1, b1, nullptr, hbuf, ROWS, D_FF, D_MODEL);
    gemm_kernel<false, true ><<<gProj, 256, GSMEM_BYTES>>>(hbuf, W2, b2, xres, out, ROWS, D_MODEL, D_FF);
}

// round 13
// speedup vs baseline: 5.1607x; 1.5175x over previous
#include <cuda_runtime.h>
#include <cuda_fp16.h>
#include <math.h>

#define D_MODEL 1024
#define D_FF    2048
#define BATCH   4
#define SEQ     2048
#define HEADS   16
#define DK      64
#define ROWS    (BATCH * SEQ)   // 8192

// ---------------- scratch (no allocs allowed -> __device__ globals) ----------
__device__ __half g_x2h [ROWS * D_MODEL];
__device__ __half g_qh  [ROWS * D_MODEL];
__device__ __half g_kh  [ROWS * D_MODEL];
__device__ __half g_vh  [ROWS * D_MODEL];
__device__ __half g_attnh[ROWS * D_MODEL];
__device__ __half g_hh  [ROWS * D_FF];
__device__ float  g_xres[ROWS * D_MODEL];
__device__ __half g_Wqh[D_MODEL * D_MODEL];
__device__ __half g_Wkh[D_MODEL * D_MODEL];
__device__ __half g_Wvh[D_MODEL * D_MODEL];
__device__ __half g_Woh[D_MODEL * D_MODEL];
__device__ __half g_W1h[D_FF * D_MODEL];
__device__ __half g_W2h[D_MODEL * D_FF];

struct __align__(8) H2X2 { __half2 a, b; };

// ---------------- helpers ----------------------------------------------------
__device__ __forceinline__ void cp16(void* s, const void* g) {
    unsigned sa = (unsigned)__cvta_generic_to_shared(s);
    asm volatile("cp.async.cg.shared.global [%0], [%1], 16;" :: "r"(sa), "l"(g));
}

__device__ __forceinline__ void ldsm4(unsigned& r0, unsigned& r1,
                                      unsigned& r2, unsigned& r3, const void* p) {
    unsigned a = (unsigned)__cvta_generic_to_shared(p);
    asm volatile("ldmatrix.sync.aligned.m8n8.x4.shared.b16 {%0,%1,%2,%3}, [%4];"
                 : "=r"(r0), "=r"(r1), "=r"(r2), "=r"(r3) : "r"(a));
}

__device__ __forceinline__ void ldsm4t(unsigned& r0, unsigned& r1,
                                       unsigned& r2, unsigned& r3, const void* p) {
    unsigned a = (unsigned)__cvta_generic_to_shared(p);
    asm volatile("ldmatrix.sync.aligned.m8n8.x4.trans.shared.b16 {%0,%1,%2,%3}, [%4];"
                 : "=r"(r0), "=r"(r1), "=r"(r2), "=r"(r3) : "r"(a));
}

__device__ __forceinline__ void mma16816(float* d, const unsigned* a,
                                         unsigned b0, unsigned b1) {
    asm volatile(
        "mma.sync.aligned.m16n8k16.row.col.f32.f16.f16.f32 "
        "{%0,%1,%2,%3}, {%4,%5,%6,%7}, {%8,%9}, {%0,%1,%2,%3};"
        : "+f"(d[0]), "+f"(d[1]), "+f"(d[2]), "+f"(d[3])
        : "r"(a[0]), "r"(a[1]), "r"(a[2]), "r"(a[3]), "r"(b0), "r"(b1));
}

__device__ __forceinline__ unsigned pack_h2(float lo, float hi) {
    __half2 h = __floats2half2_rn(lo, hi);
    return *(unsigned*)&h;
}

// swizzled smem layout for 64-half (128B) rows: conflict-free ldmatrix + cp.async
#define HSW(r, c) ((r) * 64 + ((((c) >> 3) ^ ((r) & 7)) << 3) + ((c) & 7))

// ---------------- fp32 -> fp16 conversion (weights) --------------------------
__global__ void f2h_kernel(const float4* __restrict__ src, H2X2* __restrict__ dst, int n4) {
    int i = blockIdx.x * blockDim.x + threadIdx.x;
    if (i < n4) {
        float4 v = src[i];
        H2X2 o;
        o.a = __floats2half2_rn(v.x, v.y);
        o.b = __floats2half2_rn(v.z, v.w);
        dst[i] = o;
    }
}

// ---------------- LayerNorm (fp32 in, fp16 out) ------------------------------
__global__ void __launch_bounds__(256) norm_kernel(
    const float* __restrict__ x, const float* __restrict__ alpha,
    const float* __restrict__ bias, __half* __restrict__ out)
{
    const int row = blockIdx.x;
    const int t = threadIdx.x;
    const float4* xr = (const float4*)(x + (size_t)row * D_MODEL);
    float4 v = xr[t];
    float s  = v.x + v.y + v.z + v.w;
    float ss = v.x*v.x + v.y*v.y + v.z*v.z + v.w*v.w;
    #pragma unroll
    for (int o = 16; o; o >>= 1) {
        s  += __shfl_xor_sync(0xffffffffu, s, o);
        ss += __shfl_xor_sync(0xffffffffu, ss, o);
    }
    __shared__ float rs[8], rss[8];
    __shared__ float s_mu, s_inv;
    const int w = t >> 5, l = t & 31;
    if (l == 0) { rs[w] = s; rss[w] = ss; }
    __syncthreads();
    if (t == 0) {
        float S = 0.f, SS = 0.f;
        #pragma unroll
        for (int i = 0; i < 8; i++) { S += rs[i]; SS += rss[i]; }
        float mu  = S * (1.0f / D_MODEL);
        float var = (SS - (float)D_MODEL * mu * mu) * (1.0f / (D_MODEL - 1));
        s_mu  = mu;
        s_inv = 1.0f / (sqrtf(fmaxf(var, 0.f)) + 1e-6f);
    }
    __syncthreads();
    const float mu = s_mu, inv = s_inv;
    float4 av = ((const float4*)alpha)[t];
    float4 bv = ((const float4*)bias)[t];
    H2X2 o;
    o.a = __floats2half2_rn(av.x * (v.x - mu) * inv + bv.x,
                            av.y * (v.y - mu) * inv + bv.y);
    o.b = __floats2half2_rn(av.z * (v.z - mu) * inv + bv.z,
                            av.w * (v.w - mu) * inv + bv.w);
    ((H2X2*)(out + (size_t)row * D_MODEL))[t] = o;
}

// ---------------- fp16 tensor-core GEMM --------------------------------------
// C[M,N] = A[M,K] @ W[N,K]^T + bias (+relu) (+residual fp32) -> fp32 or fp16 out
// CTA 128x128, k-chunk 64, 8 warps (2Mx4N), warp 64x32, mma m16n8k16.
#define HG_BUF 8192                       // halfs per (128x64) buffer
#define HG_SMEM_BYTES (4 * HG_BUF * 2)    // A0,A1,B0,B1 = 64KB

template<bool RELU, bool RES, bool HOUT>
__global__ void __launch_bounds__(256, 2) hgemm_kernel(
    const __half* __restrict__ A, const __half* __restrict__ W,
    const float* __restrict__ bias, const float* __restrict__ R,
    float* __restrict__ C, __half* __restrict__ Ch, int M, int N, int K)
{
    extern __shared__ __half hsm[];
    __half* Ab[2] = { hsm,              hsm + HG_BUF };
    __half* Bb[2] = { hsm + 2*HG_BUF,   hsm + 3*HG_BUF };

    const int m0 = blockIdx.y * 128, n0 = blockIdx.x * 128;
    const int tid  = threadIdx.x;
    const int lane = tid & 31;
    const int warp = tid >> 5;
    const int wm = warp >> 2;        // 0..1
    const int wn = warp & 3;         // 0..3

    int lrow[4], lch[4];
    #pragma unroll
    for (int l = 0; l < 4; l++) {
        int idx = tid + l * 256;     // 0..1023
        lrow[l] = idx >> 3;          // 0..127
        lch[l]  = idx & 7;           // 16B chunk
    }

    const int KT = K >> 6;           // K / 64

    #pragma unroll
    for (int l = 0; l < 4; l++) {
        cp16(&Ab[0][HSW(lrow[l], lch[l]*8)], A + (size_t)(m0 + lrow[l])*K + lch[l]*8);
        cp16(&Bb[0][HSW(lrow[l], lch[l]*8)], W + (size_t)(n0 + lrow[l])*K + lch[l]*8);
    }
    asm volatile("cp.async.commit_group;");

    float acc[4][4][4] = {};

    for (int kt = 0; kt < KT; kt++) {
        if (kt + 1 < KT) {
            const int k0 = (kt + 1) << 6;
            __half* An = Ab[(kt + 1) & 1];
            __half* Bn = Bb[(kt + 1) & 1];
            #pragma unroll
            for (int l = 0; l < 4; l++) {
                cp16(&An[HSW(lrow[l], lch[l]*8)], A + (size_t)(m0 + lrow[l])*K + k0 + lch[l]*8);
                cp16(&Bn[HSW(lrow[l], lch[l]*8)], W + (size_t)(n0 + lrow[l])*K + k0 + lch[l]*8);
            }
            asm volatile("cp.async.commit_group;");
            asm volatile("cp.async.wait_group 1;");
        } else {
            asm volatile("cp.async.wait_group 0;");
        }
        __syncthreads();

        const __half* At = Ab[kt & 1];
        const __half* Bt = Bb[kt & 1];
        const int fr = lane & 15;
        const int fc = (lane >> 4) << 3;

        #pragma unroll
        for (int s = 0; s < 4; s++) {
            unsigned af[4][4];
            #pragma unroll
            for (int i = 0; i < 4; i++)
                ldsm4(af[i][0], af[i][1], af[i][2], af[i][3],
                      &At[HSW(wm*64 + i*16 + fr, s*16 + fc)]);
            unsigned bfr[4][2];
            #pragma unroll
            for (int j = 0; j < 2; j++) {
                unsigned r0, r1, r2, r3;
                ldsm4(r0, r1, r2, r3, &Bt[HSW(wn*32 + j*16 + fr, s*16 + fc)]);
                bfr[2*j][0]   = r0; bfr[2*j][1]   = r2;
                bfr[2*j+1][0] = r1; bfr[2*j+1][1] = r3;
            }
            #pragma unroll
            for (int i = 0; i < 4; i++)
                #pragma unroll
                for (int j = 0; j < 4; j++)
                    mma16816(acc[i][j], af[i], bfr[j][0], bfr[j][1]);
        }
        __syncthreads();
    }

    const int lr = lane >> 2, lc = lane & 3;
    #pragma unroll
    for (int i = 0; i < 4; i++) {
        const int m = m0 + wm*64 + i*16 + lr;
        #pragma unroll
        for (int j = 0; j < 4; j++) {
            const int n = n0 + wn*32 + j*8 + lc*2;
            const float bx = bias[n], by = bias[n + 1];
            float v0 = acc[i][j][0] + bx, v1 = acc[i][j][1] + by;
            float v2 = acc[i][j][2] + bx, v3 = acc[i][j][3] + by;
            if (RELU) {
                v0 = fmaxf(v0, 0.f); v1 = fmaxf(v1, 0.f);
                v2 = fmaxf(v2, 0.f); v3 = fmaxf(v3, 0.f);
            }
            if (RES) {
                float2 r0 = *(const float2*)(R + (size_t)m*N + n);
                float2 r1 = *(const float2*)(R + (size_t)(m+8)*N + n);
                v0 += r0.x; v1 += r0.y; v2 += r1.x; v3 += r1.y;
            }
            if (HOUT) {
                *(__half2*)(Ch + (size_t)m*N + n)     = __floats2half2_rn(v0, v1);
                *(__half2*)(Ch + (size_t)(m+8)*N + n) = __floats2half2_rn(v2, v3);
            } else {
                *(float2*)(C + (size_t)m*N + n)     = make_float2(v0, v1);
                *(float2*)(C + (size_t)(m+8)*N + n) = make_float2(v2, v3);
            }
        }
    }
}

// ---------------- fp16 flash attention ---------------------------------------
// CTA: 128 queries (8 warps x m16), BK=64 key tiles, mma m16n8k16.
// smem halfs: Q[128x64] | K[2][64x64] | V[2][64x64] | mask int[2][64]
#define FQ_OFF 0
#define FK_OFF 8192
#define FV_OFF 16384
#define FM_H   24576                       // halfs before mask ints
#define FL_SMEM_BYTES (FM_H * 2 + 2 * 64 * 4)
#define FL_NT (SEQ / 64)

__global__ void __launch_bounds__(256, 2) flash_kernel(
    const __half* __restrict__ Q, const __half* __restrict__ Kg,
    const __half* __restrict__ Vg, const int* __restrict__ mask,
    __half* __restrict__ O)
{
    extern __shared__ __half hsm[];
    __half* Qs = hsm + FQ_OFF;
    __half* Ks = hsm + FK_OFF;             // 2 x 4096
    __half* Vs = hsm + FV_OFF;             // 2 x 4096
    int*    mk = (int*)(hsm + FM_H);       // 2 x 64

    const int qt = blockIdx.x, h = blockIdx.y, b = blockIdx.z;
    const int tid = threadIdx.x, lane = tid & 31, warp = tid >> 5;
    const int lr = lane >> 2, lc = lane & 3;
    const int fr = lane & 15, fc = (lane >> 4) << 3;
    const size_t rb = (size_t)b * SEQ;
    const int hb = h * DK;
    const int q0 = qt * 128;

    // load maps
    int qrow[4], qch[4], krow[2], kch[2];
    #pragma unroll
    for (int l = 0; l < 4; l++) {
        int idx = tid + l * 256;
        qrow[l] = idx >> 3; qch[l] = idx & 7;
    }
    #pragma unroll
    for (int l = 0; l < 2; l++) {
        int idx = tid + l * 256;
        krow[l] = idx >> 3; kch[l] = idx & 7;
    }

    // prologue: Q tile + K0/V0 + mask0
    #pragma unroll
    for (int l = 0; l < 4; l++)
        cp16(&Qs[HSW(qrow[l], qch[l]*8)], Q + (rb + q0 + qrow[l])*D_MODEL + hb + qch[l]*8);
    #pragma unroll
    for (int l = 0; l < 2; l++) {
        cp16(&Ks[HSW(krow[l], kch[l]*8)], Kg + (rb + krow[l])*D_MODEL + hb + kch[l]*8);
        cp16(&Vs[HSW(krow[l], kch[l]*8)], Vg + (rb + krow[l])*D_MODEL + hb + kch[l]*8);
    }
    if (tid < 16) cp16(&mk[tid*4], mask + b*SEQ + tid*4);
    asm volatile("cp.async.commit_group;");
    asm volatile("cp.async.wait_group 0;");
    __syncthreads();

    // Q fragments (scaled by 1/sqrt(dk) = 0.125 exactly)
    unsigned qf[4][4];
    {
        const __half2 s8 = __float2half2_rn(0.125f);
        #pragma unroll
        for (int s = 0; s < 4; s++) {
            ldsm4(qf[s][0], qf[s][1], qf[s][2], qf[s][3],
                  &Qs[HSW(warp*16 + fr, s*16 + fc)]);
            #pragma unroll
            for (int r = 0; r < 4; r++) {
                __half2 t = *(__half2*)&qf[s][r];
                t = __hmul2(t, s8);
                qf[s][r] = *(unsigned*)&t;
            }
        }
    }

    float oacc[8][4] = {};
    float m0 = -1e30f, m1 = -1e30f, l0 = 0.f, l1 = 0.f;

    for (int kt = 0; kt < FL_NT; kt++) {
        const int cur = kt & 1, nxt = cur ^ 1;

        if (kt + 1 < FL_NT) {
            const int k0n = (kt + 1) * 64;
            #pragma unroll
            for (int l = 0; l < 2; l++) {
                cp16(&Ks[nxt*4096 + HSW(krow[l], kch[l]*8)],
                     Kg + (rb + k0n + krow[l])*D_MODEL + hb + kch[l]*8);
                cp16(&Vs[nxt*4096 + HSW(krow[l], kch[l]*8)],
                     Vg + (rb + k0n + krow[l])*D_MODEL + hb + kch[l]*8);
            }
            if (tid < 16) cp16(&mk[nxt*64 + tid*4], mask + b*SEQ + k0n + tid*4);
            asm volatile("cp.async.commit_group;");
            asm volatile("cp.async.wait_group 1;");
        } else {
            asm volatile("cp.async.wait_group 0;");
        }
        __syncthreads();

        const __half* Kc = Ks + cur*4096;
        const __half* Vc = Vs + cur*4096;
        const int*    mc = mk + cur*64;

        // S = (Q*0.125) @ K^T
        float sa[8][4] = {};
        #pragma unroll
        for (int s = 0; s < 4; s++) {
            #pragma unroll
            for (int jj = 0; jj < 4; jj++) {
                unsigned r0, r1, r2, r3;
                ldsm4(r0, r1, r2, r3, &Kc[HSW(jj*16 + fr, s*16 + fc)]);
                mma16816(sa[2*jj],   qf[s], r0, r2);
                mma16816(sa[2*jj+1], qf[s], r1, r3);
            }
        }

        // mask bias + row max
        float mx0 = m0, mx1 = m1;
        #pragma unroll
        for (int nb = 0; nb < 8; nb++) {
            int2 mm = *(const int2*)&mc[nb*8 + 2*lc];
            float b0 = (mm.x == 1) ? -1e30f : 0.f;
            float b1 = (mm.y == 1) ? -1e30f : 0.f;
            sa[nb][0] += b0; sa[nb][1] += b1;
            sa[nb][2] += b0; sa[nb][3] += b1;
            mx0 = fmaxf(mx0, fmaxf(sa[nb][0], sa[nb][1]));
            mx1 = fmaxf(mx1, fmaxf(sa[nb][2], sa[nb][3]));
        }
        mx0 = fmaxf(mx0, __shfl_xor_sync(0xffffffffu, mx0, 1));
        mx0 = fmaxf(mx0, __shfl_xor_sync(0xffffffffu, mx0, 2));
        mx1 = fmaxf(mx1, __shfl_xor_sync(0xffffffffu, mx1, 1));
        mx1 = fmaxf(mx1, __shfl_xor_sync(0xffffffffu, mx1, 2));

        const float corr0 = __expf(m0 - mx0);
        const float corr1 = __expf(m1 - mx1);
        float sum0 = 0.f, sum1 = 0.f;
        #pragma unroll
        for (int nb = 0; nb < 8; nb++) {
            sa[nb][0] = __expf(sa[nb][0] - mx0);
            sa[nb][1] = __expf(sa[nb][1] - mx0);
            sa[nb][2] = __expf(sa[nb][2] - mx1);
            sa[nb][3] = __expf(sa[nb][3] - mx1);
            sum0 += sa[nb][0] + sa[nb][1];
            sum1 += sa[nb][2] + sa[nb][3];
        }
        sum0 += __shfl_xor_sync(0xffffffffu, sum0, 1);
        sum0 += __shfl_xor_sync(0xffffffffu, sum0, 2);
        sum1 += __shfl_xor_sync(0xffffffffu, sum1, 1);
        sum1 += __shfl_xor_sync(0xffffffffu, sum1, 2);
        l0 = l0 * corr0 + sum0; m0 = mx0;
        l1 = l1 * corr1 + sum1; m1 = mx1;

        #pragma unroll
        for (int d = 0; d < 8; d++) {
            oacc[d][0] *= corr0; oacc[d][1] *= corr0;
            oacc[d][2] *= corr1; oacc[d][3] *= corr1;
        }

        // P @ V : S C-fragments ARE the fp16 A-fragments after packing
        #pragma unroll
        for (int s = 0; s < 4; s++) {
            unsigned pa[4];
            pa[0] = pack_h2(sa[2*s][0],   sa[2*s][1]);
            pa[1] = pack_h2(sa[2*s][2],   sa[2*s][3]);
            pa[2] = pack_h2(sa[2*s+1][0], sa[2*s+1][1]);
            pa[3] = pack_h2(sa[2*s+1][2], sa[2*s+1][3]);
            #pragma unroll
            for (int dp = 0; dp < 4; dp++) {
                unsigned r0, r1, r2, r3;
                ldsm4t(r0, r1, r2, r3, &Vc[HSW(s*16 + fr, dp*16 + fc)]);
                mma16816(oacc[2*dp],   pa, r0, r1);
                mma16816(oacc[2*dp+1], pa, r2, r3);
            }
        }
        __syncthreads();
    }

    // epilogue (fp16 out)
    const float inv0 = 1.0f / l0, inv1 = 1.0f / l1;
    const int row = q0 + warp*16 + lr;
    __half* OA = O + (rb + row) * D_MODEL + hb;
    __half* OB = OA + 8 * D_MODEL;
    #pragma unroll
    for (int d = 0; d < 8; d++) {
        *(__half2*)(OA + d*8 + 2*lc) = __floats2half2_rn(oacc[d][0]*inv0, oacc[d][1]*inv0);
        *(__half2*)(OB + d*8 + 2*lc) = __floats2half2_rn(oacc[d][2]*inv1, oacc[d][3]*inv1);
    }
}

// ---------------- orchestration ---------------------------------------------
extern "C" void kernel_launch(void* const* d_in, const int* in_sizes, int n_in,
                              void* d_out, int out_size)
{
    const float* x      = (const float*)d_in[0];
    const int*   mask   = (const int*)  d_in[1];
    const float* alpha1 = (const float*)d_in[2];
    const float* bias1  = (const float*)d_in[3];
    const float* alpha2 = (const float*)d_in[4];
    const float* bias2  = (const float*)d_in[5];
    const float* Wq = (const float*)d_in[6];   const float* bq = (const float*)d_in[7];
    const float* Wk = (const float*)d_in[8];   const float* bk = (const float*)d_in[9];
    const float* Wv = (const float*)d_in[10];  const float* bv = (const float*)d_in[11];
    const float* Wo = (const float*)d_in[12];  const float* bo = (const float*)d_in[13];
    const float* W1 = (const float*)d_in[14];  const float* b1 = (const float*)d_in[15];
    const float* W2 = (const float*)d_in[16];  const float* b2 = (const float*)d_in[17];
    float* out = (float*)d_out;

    __half *x2h, *qh, *kh, *vh, *attnh, *hh;
    __half *Wqh, *Wkh, *Wvh, *Woh, *W1h, *W2h;
    float  *xres;
    cudaGetSymbolAddress((void**)&x2h,   g_x2h);
    cudaGetSymbolAddress((void**)&qh,    g_qh);
    cudaGetSymbolAddress((void**)&kh,    g_kh);
    cudaGetSymbolAddress((void**)&vh,    g_vh);
    cudaGetSymbolAddress((void**)&attnh, g_attnh);
    cudaGetSymbolAddress((void**)&hh,    g_hh);
    cudaGetSymbolAddress((void**)&xres,  g_xres);
    cudaGetSymbolAddress((void**)&Wqh,   g_Wqh);
    cudaGetSymbolAddress((void**)&Wkh,   g_Wkh);
    cudaGetSymbolAddress((void**)&Wvh,   g_Wvh);
    cudaGetSymbolAddress((void**)&Woh,   g_Woh);
    cudaGetSymbolAddress((void**)&W1h,   g_W1h);
    cudaGetSymbolAddress((void**)&W2h,   g_W2h);

    cudaFuncSetAttribute(flash_kernel,
                         cudaFuncAttributeMaxDynamicSharedMemorySize, FL_SMEM_BYTES);
    cudaFuncSetAttribute(hgemm_kernel<false, false, true>,
                         cudaFuncAttributeMaxDynamicSharedMemorySize, HG_SMEM_BYTES);
    cudaFuncSetAttribute(hgemm_kernel<false, true, false>,
                         cudaFuncAttributeMaxDynamicSharedMemorySize, HG_SMEM_BYTES);
    cudaFuncSetAttribute(hgemm_kernel<true, false, true>,
                         cudaFuncAttributeMaxDynamicSharedMemorySize, HG_SMEM_BYTES);

    // weight conversion (fp32 -> fp16), once per launch
    const int nP4 = D_MODEL * D_MODEL / 4;     // 262144
    const int nF4 = D_FF * D_MODEL / 4;        // 524288
    f2h_kernel<<<nP4 / 256, 256>>>((const float4*)Wq, (H2X2*)Wqh, nP4);
    f2h_kernel<<<nP4 / 256, 256>>>((const float4*)Wk, (H2X2*)Wkh, nP4);
    f2h_kernel<<<nP4 / 256, 256>>>((const float4*)Wv, (H2X2*)Wvh, nP4);
    f2h_kernel<<<nP4 / 256, 256>>>((const float4*)Wo, (H2X2*)Woh, nP4);
    f2h_kernel<<<nF4 / 256, 256>>>((const float4*)W1, (H2X2*)W1h, nF4);
    f2h_kernel<<<nF4 / 256, 256>>>((const float4*)W2, (H2X2*)W2h, nF4);

    const dim3 gProj(D_MODEL / 128, ROWS / 128);   // (8, 64)
    const dim3 gFF1 (D_FF    / 128, ROWS / 128);   // (16, 64)

    norm_kernel<<<ROWS, 256>>>(x, alpha1, bias1, x2h);
    hgemm_kernel<false, false, true><<<gProj, 256, HG_SMEM_BYTES>>>(
        x2h, Wqh, bq, nullptr, nullptr, qh, ROWS, D_MODEL, D_MODEL);
    hgemm_kernel<false, false, true><<<gProj, 256, HG_SMEM_BYTES>>>(
        x2h, Wkh, bk, nullptr, nullptr, kh, ROWS, D_MODEL, D_MODEL);
    hgemm_kernel<false, false, true><<<gProj, 256, HG_SMEM_BYTES>>>(
        x2h, Wvh, bv, nullptr, nullptr, vh, ROWS, D_MODEL, D_MODEL);
    flash_kernel<<<dim3(SEQ / 128, HEADS, BATCH), 256, FL_SMEM_BYTES>>>(
        qh, kh, vh, mask, attnh);
    hgemm_kernel<false, true, false><<<gProj, 256, HG_SMEM_BYTES>>>(
        attnh, Woh, bo, x, xres, nullptr, ROWS, D_MODEL, D_MODEL);
    norm_kernel<<<ROWS, 256>>>(xres, alpha2, bias2, x2h);
    hgemm_kernel<true, false, true><<<gFF1, 256, HG_SMEM_BYTES>>>(
        x2h, W1h, b1, nullptr, nullptr, hh, ROWS, D_FF, D_MODEL);
    hgemm_kernel<false, true, false><<<gProj, 256, HG_SMEM_BYTES>>>(
        hh, W2h, b2, xres, out, nullptr, ROWS, D_MODEL, D_FF);
}

// round 14
// speedup vs baseline: 8.2859x; 1.6056x over previous
#include <cuda_runtime.h>
#include <cuda_fp16.h>
#include <math.h>

#define D_MODEL 1024
#define D_FF    2048
#define BATCH   4
#define SEQ     2048
#define HEADS   16
#define DK      64
#define ROWS    (BATCH * SEQ)   // 8192

// ---------------- scratch (no allocs allowed -> __device__ globals) ----------
__device__ __half g_x2h [ROWS * D_MODEL];
__device__ __half g_qh  [ROWS * D_MODEL];
__device__ __half g_kh  [ROWS * D_MODEL];
__device__ __half g_vh  [ROWS * D_MODEL];
__device__ __half g_attnh[ROWS * D_MODEL];
__device__ __half g_hh  [ROWS * D_FF];
__device__ float  g_xres[ROWS * D_MODEL];
__device__ __half g_Wqkvh[3 * D_MODEL * D_MODEL];   // Wq | Wk | Wv concatenated
__device__ __half g_Woh[D_MODEL * D_MODEL];
__device__ __half g_W1h[D_FF * D_MODEL];
__device__ __half g_W2h[D_MODEL * D_FF];

struct __align__(8) H2X2 { __half2 a, b; };

// ---------------- helpers ----------------------------------------------------
__device__ __forceinline__ void cp16(void* s, const void* g) {
    unsigned sa = (unsigned)__cvta_generic_to_shared(s);
    asm volatile("cp.async.cg.shared.global [%0], [%1], 16;" :: "r"(sa), "l"(g));
}

__device__ __forceinline__ void ldsm4(unsigned& r0, unsigned& r1,
                                      unsigned& r2, unsigned& r3, const void* p) {
    unsigned a = (unsigned)__cvta_generic_to_shared(p);
    asm volatile("ldmatrix.sync.aligned.m8n8.x4.shared.b16 {%0,%1,%2,%3}, [%4];"
                 : "=r"(r0), "=r"(r1), "=r"(r2), "=r"(r3) : "r"(a));
}

__device__ __forceinline__ void ldsm4t(unsigned& r0, unsigned& r1,
                                       unsigned& r2, unsigned& r3, const void* p) {
    unsigned a = (unsigned)__cvta_generic_to_shared(p);
    asm volatile("ldmatrix.sync.aligned.m8n8.x4.trans.shared.b16 {%0,%1,%2,%3}, [%4];"
                 : "=r"(r0), "=r"(r1), "=r"(r2), "=r"(r3) : "r"(a));
}

__device__ __forceinline__ void mma16816(float* d, const unsigned* a,
                                         unsigned b0, unsigned b1) {
    asm volatile(
        "mma.sync.aligned.m16n8k16.row.col.f32.f16.f16.f32 "
        "{%0,%1,%2,%3}, {%4,%5,%6,%7}, {%8,%9}, {%0,%1,%2,%3};"
        : "+f"(d[0]), "+f"(d[1]), "+f"(d[2]), "+f"(d[3])
        : "r"(a[0]), "r"(a[1]), "r"(a[2]), "r"(a[3]), "r"(b0), "r"(b1));
}

__device__ __forceinline__ unsigned pack_h2(float lo, float hi) {
    __half2 h = __floats2half2_rn(lo, hi);
    return *(unsigned*)&h;
}

// swizzled smem layout for 64-half (128B) rows: conflict-free ldmatrix + cp.async
#define HSW(r, c) ((r) * 64 + ((((c) >> 3) ^ ((r) & 7)) << 3) + ((c) & 7))

// ---------------- fused fp32 -> fp16 weight conversion ------------------------
#define NP4 (D_MODEL * D_MODEL / 4)        // 262144 float4 per 1024x1024 weight
#define NF4 (D_FF * D_MODEL / 4)           // 524288 float4 per 2048x1024 weight

__device__ __forceinline__ H2X2 f2h4(float4 v) {
    H2X2 o;
    o.a = __floats2half2_rn(v.x, v.y);
    o.b = __floats2half2_rn(v.z, v.w);
    return o;
}

// Wq|Wk|Wv -> g_Wqkvh (one launch)
__global__ void f2h_qkv_kernel(const float4* __restrict__ Wq,
                               const float4* __restrict__ Wk,
                               const float4* __restrict__ Wv,
                               H2X2* __restrict__ dst) {
    int i = blockIdx.x * blockDim.x + threadIdx.x;   // 0 .. 3*NP4-1
    int w = i / NP4, j = i - w * NP4;
    const float4* src = (w == 0) ? Wq : (w == 1) ? Wk : Wv;
    dst[i] = f2h4(src[j]);
}

// Wo, W1, W2 -> g_Woh, g_W1h, g_W2h (one launch)
__global__ void f2h_rest_kernel(const float4* __restrict__ Wo,
                                const float4* __restrict__ W1,
                                const float4* __restrict__ W2,
                                H2X2* __restrict__ dWo, H2X2* __restrict__ dW1,
                                H2X2* __restrict__ dW2) {
    int i = blockIdx.x * blockDim.x + threadIdx.x;   // 0 .. NP4+2*NF4-1
    if (i < NP4) {
        dWo[i] = f2h4(Wo[i]);
    } else if (i < NP4 + NF4) {
        dW1[i - NP4] = f2h4(W1[i - NP4]);
    } else {
        dW2[i - NP4 - NF4] = f2h4(W2[i - NP4 - NF4]);
    }
}

// ---------------- LayerNorm (fp32 in, fp16 out) ------------------------------
__global__ void __launch_bounds__(256) norm_kernel(
    const float* __restrict__ x, const float* __restrict__ alpha,
    const float* __restrict__ bias, __half* __restrict__ out)
{
    const int row = blockIdx.x;
    const int t = threadIdx.x;
    const float4* xr = (const float4*)(x + (size_t)row * D_MODEL);
    float4 v = xr[t];
    float s  = v.x + v.y + v.z + v.w;
    float ss = v.x*v.x + v.y*v.y + v.z*v.z + v.w*v.w;
    #pragma unroll
    for (int o = 16; o; o >>= 1) {
        s  += __shfl_xor_sync(0xffffffffu, s, o);
        ss += __shfl_xor_sync(0xffffffffu, ss, o);
    }
    __shared__ float rs[8], rss[8];
    __shared__ float s_mu, s_inv;
    const int w = t >> 5, l = t & 31;
    if (l == 0) { rs[w] = s; rss[w] = ss; }
    __syncthreads();
    if (t == 0) {
        float S = 0.f, SS = 0.f;
        #pragma unroll
        for (int i = 0; i < 8; i++) { S += rs[i]; SS += rss[i]; }
        float mu  = S * (1.0f / D_MODEL);
        float var = (SS - (float)D_MODEL * mu * mu) * (1.0f / (D_MODEL - 1));
        s_mu  = mu;
        s_inv = 1.0f / (sqrtf(fmaxf(var, 0.f)) + 1e-6f);
    }
    __syncthreads();
    const float mu = s_mu, inv = s_inv;
    float4 av = ((const float4*)alpha)[t];
    float4 bv = ((const float4*)bias)[t];
    H2X2 o;
    o.a = __floats2half2_rn(av.x * (v.x - mu) * inv + bv.x,
                            av.y * (v.y - mu) * inv + bv.y);
    o.b = __floats2half2_rn(av.z * (v.z - mu) * inv + bv.z,
                            av.w * (v.w - mu) * inv + bv.w);
    ((H2X2*)(out + (size_t)row * D_MODEL))[t] = o;
}

// ---------------- fp16 tensor-core GEMM --------------------------------------
// C[M,N] = A[M,K] @ W[N,K]^T + bias (+relu) (+residual fp32) -> fp32 or fp16 out
// CTA 128x128, k-chunk 64, 8 warps (2Mx4N), warp 64x32, mma m16n8k16.
#define HG_BUF 8192                       // halfs per (128x64) buffer
#define HG_SMEM_BYTES (4 * HG_BUF * 2)    // A0,A1,B0,B1 = 64KB

template<bool RELU, bool RES, bool HOUT>
__global__ void __launch_bounds__(256, 2) hgemm_kernel(
    const __half* __restrict__ A, const __half* __restrict__ W,
    const float* __restrict__ bias, const float* __restrict__ R,
    float* __restrict__ C, __half* __restrict__ Ch, int M, int N, int K)
{
    extern __shared__ __half hsm[];
    __half* Ab[2] = { hsm,              hsm + HG_BUF };
    __half* Bb[2] = { hsm + 2*HG_BUF,   hsm + 3*HG_BUF };

    const int m0 = blockIdx.y * 128, n0 = blockIdx.x * 128;
    const int tid  = threadIdx.x;
    const int lane = tid & 31;
    const int warp = tid >> 5;
    const int wm = warp >> 2;
    const int wn = warp & 3;

    int lrow[4], lch[4];
    #pragma unroll
    for (int l = 0; l < 4; l++) {
        int idx = tid + l * 256;
        lrow[l] = idx >> 3;
        lch[l]  = idx & 7;
    }

    const int KT = K >> 6;

    #pragma unroll
    for (int l = 0; l < 4; l++) {
        cp16(&Ab[0][HSW(lrow[l], lch[l]*8)], A + (size_t)(m0 + lrow[l])*K + lch[l]*8);
        cp16(&Bb[0][HSW(lrow[l], lch[l]*8)], W + (size_t)(n0 + lrow[l])*K + lch[l]*8);
    }
    asm volatile("cp.async.commit_group;");

    float acc[4][4][4] = {};

    for (int kt = 0; kt < KT; kt++) {
        if (kt + 1 < KT) {
            const int k0 = (kt + 1) << 6;
            __half* An = Ab[(kt + 1) & 1];
            __half* Bn = Bb[(kt + 1) & 1];
            #pragma unroll
            for (int l = 0; l < 4; l++) {
                cp16(&An[HSW(lrow[l], lch[l]*8)], A + (size_t)(m0 + lrow[l])*K + k0 + lch[l]*8);
                cp16(&Bn[HSW(lrow[l], lch[l]*8)], W + (size_t)(n0 + lrow[l])*K + k0 + lch[l]*8);
            }
            asm volatile("cp.async.commit_group;");
            asm volatile("cp.async.wait_group 1;");
        } else {
            asm volatile("cp.async.wait_group 0;");
        }
        __syncthreads();

        const __half* At = Ab[kt & 1];
        const __half* Bt = Bb[kt & 1];
        const int fr = lane & 15;
        const int fc = (lane >> 4) << 3;

        #pragma unroll
        for (int s = 0; s < 4; s++) {
            unsigned af[4][4];
            #pragma unroll
            for (int i = 0; i < 4; i++)
                ldsm4(af[i][0], af[i][1], af[i][2], af[i][3],
                      &At[HSW(wm*64 + i*16 + fr, s*16 + fc)]);
            unsigned bfr[4][2];
            #pragma unroll
            for (int j = 0; j < 2; j++) {
                unsigned r0, r1, r2, r3;
                ldsm4(r0, r1, r2, r3, &Bt[HSW(wn*32 + j*16 + fr, s*16 + fc)]);
                bfr[2*j][0]   = r0; bfr[2*j][1]   = r2;
                bfr[2*j+1][0] = r1; bfr[2*j+1][1] = r3;
            }
            #pragma unroll
            for (int i = 0; i < 4; i++)
                #pragma unroll
                for (int j = 0; j < 4; j++)
                    mma16816(acc[i][j], af[i], bfr[j][0], bfr[j][1]);
        }
        __syncthreads();
    }

    const int lr = lane >> 2, lc = lane & 3;
    #pragma unroll
    for (int i = 0; i < 4; i++) {
        const int m = m0 + wm*64 + i*16 + lr;
        #pragma unroll
        for (int j = 0; j < 4; j++) {
            const int n = n0 + wn*32 + j*8 + lc*2;
            const float bx = bias[n], by = bias[n + 1];
            float v0 = acc[i][j][0] + bx, v1 = acc[i][j][1] + by;
            float v2 = acc[i][j][2] + bx, v3 = acc[i][j][3] + by;
            if (RELU) {
                v0 = fmaxf(v0, 0.f); v1 = fmaxf(v1, 0.f);
                v2 = fmaxf(v2, 0.f); v3 = fmaxf(v3, 0.f);
            }
            if (RES) {
                float2 r0 = *(const float2*)(R + (size_t)m*N + n);
                float2 r1 = *(const float2*)(R + (size_t)(m+8)*N + n);
                v0 += r0.x; v1 += r0.y; v2 += r1.x; v3 += r1.y;
            }
            if (HOUT) {
                *(__half2*)(Ch + (size_t)m*N + n)     = __floats2half2_rn(v0, v1);
                *(__half2*)(Ch + (size_t)(m+8)*N + n) = __floats2half2_rn(v2, v3);
            } else {
                *(float2*)(C + (size_t)m*N + n)     = make_float2(v0, v1);
                *(float2*)(C + (size_t)(m+8)*N + n) = make_float2(v2, v3);
            }
        }
    }
}

// ---------------- fused QKV GEMM ---------------------------------------------
// One N=3072 GEMM vs concatenated Wqkv; each CTA (128 cols) lies wholly in one
// of q/k/v (128 | 1024), so output buffer + bias selected per CTA.
__global__ void __launch_bounds__(256, 2) hgemm_qkv_kernel(
    const __half* __restrict__ A, const __half* __restrict__ W,
    const float* __restrict__ bq, const float* __restrict__ bk,
    const float* __restrict__ bv,
    __half* __restrict__ Q, __half* __restrict__ Kh, __half* __restrict__ V)
{
    const int K = D_MODEL;
    extern __shared__ __half hsm[];
    __half* Ab[2] = { hsm,              hsm + HG_BUF };
    __half* Bb[2] = { hsm + 2*HG_BUF,   hsm + 3*HG_BUF };

    const int m0 = blockIdx.y * 128, n0 = blockIdx.x * 128;
    const int sel = blockIdx.x >> 3;                 // 0..2 (8 col-blocks/1024)
    const float* bias = (sel == 0) ? bq : (sel == 1) ? bk : bv;
    __half* Ch = (sel == 0) ? Q : (sel == 1) ? Kh : V;
    const int c0 = n0 & (D_MODEL - 1);               // column within q/k/v

    const int tid  = threadIdx.x;
    const int lane = tid & 31;
    const int warp = tid >> 5;
    const int wm = warp >> 2;
    const int wn = warp & 3;

    int lrow[4], lch[4];
    #pragma unroll
    for (int l = 0; l < 4; l++) {
        int idx = tid + l * 256;
        lrow[l] = idx >> 3;
        lch[l]  = idx & 7;
    }

    const int KT = K >> 6;

    #pragma unroll
    for (int l = 0; l < 4; l++) {
        cp16(&Ab[0][HSW(lrow[l], lch[l]*8)], A + (size_t)(m0 + lrow[l])*K + lch[l]*8);
        cp16(&Bb[0][HSW(lrow[l], lch[l]*8)], W + (size_t)(n0 + lrow[l])*K + lch[l]*8);
    }
    asm volatile("cp.async.commit_group;");

    float acc[4][4][4] = {};

    for (int kt = 0; kt < KT; kt++) {
        if (kt + 1 < KT) {
            const int k0 = (kt + 1) << 6;
            __half* An = Ab[(kt + 1) & 1];
            __half* Bn = Bb[(kt + 1) & 1];
            #pragma unroll
            for (int l = 0; l < 4; l++) {
                cp16(&An[HSW(lrow[l], lch[l]*8)], A + (size_t)(m0 + lrow[l])*K + k0 + lch[l]*8);
                cp16(&Bn[HSW(lrow[l], lch[l]*8)], W + (size_t)(n0 + lrow[l])*K + k0 + lch[l]*8);
            }
            asm volatile("cp.async.commit_group;");
            asm volatile("cp.async.wait_group 1;");
        } else {
            asm volatile("cp.async.wait_group 0;");
        }
        __syncthreads();

        const __half* At = Ab[kt & 1];
        const __half* Bt = Bb[kt & 1];
        const int fr = lane & 15;
        const int fc = (lane >> 4) << 3;

        #pragma unroll
        for (int s = 0; s < 4; s++) {
            unsigned af[4][4];
            #pragma unroll
            for (int i = 0; i < 4; i++)
                ldsm4(af[i][0], af[i][1], af[i][2], af[i][3],
                      &At[HSW(wm*64 + i*16 + fr, s*16 + fc)]);
            unsigned bfr[4][2];
            #pragma unroll
            for (int j = 0; j < 2; j++) {
                unsigned r0, r1, r2, r3;
                ldsm4(r0, r1, r2, r3, &Bt[HSW(wn*32 + j*16 + fr, s*16 + fc)]);
                bfr[2*j][0]   = r0; bfr[2*j][1]   = r2;
                bfr[2*j+1][0] = r1; bfr[2*j+1][1] = r3;
            }
            #pragma unroll
            for (int i = 0; i < 4; i++)
                #pragma unroll
                for (int j = 0; j < 4; j++)
                    mma16816(acc[i][j], af[i], bfr[j][0], bfr[j][1]);
        }
        __syncthreads();
    }

    const int lr = lane >> 2, lc = lane & 3;
    #pragma unroll
    for (int i = 0; i < 4; i++) {
        const int m = m0 + wm*64 + i*16 + lr;
        #pragma unroll
        for (int j = 0; j < 4; j++) {
            const int n = c0 + wn*32 + j*8 + lc*2;
            const float bx = bias[n], by = bias[n + 1];
            float v0 = acc[i][j][0] + bx, v1 = acc[i][j][1] + by;
            float v2 = acc[i][j][2] + bx, v3 = acc[i][j][3] + by;
            *(__half2*)(Ch + (size_t)m*D_MODEL + n)     = __floats2half2_rn(v0, v1);
            *(__half2*)(Ch + (size_t)(m+8)*D_MODEL + n) = __floats2half2_rn(v2, v3);
        }
    }
}

// ---------------- fp16 flash attention ---------------------------------------
// CTA: 128 queries (8 warps x m16), BK=64 key tiles, mma m16n8k16.
// smem halfs: Q[128x64] | K[2][64x64] | V[2][64x64] | mask int[2][64]
#define FQ_OFF 0
#define FK_OFF 8192
#define FV_OFF 16384
#define FM_H   24576                       // halfs before mask ints
#define FL_SMEM_BYTES (FM_H * 2 + 2 * 64 * 4)
#define FL_NT (SEQ / 64)

__global__ void __launch_bounds__(256, 2) flash_kernel(
    const __half* __restrict__ Q, const __half* __restrict__ Kg,
    const __half* __restrict__ Vg, const int* __restrict__ mask,
    __half* __restrict__ O)
{
    extern __shared__ __half hsm[];
    __half* Qs = hsm + FQ_OFF;
    __half* Ks = hsm + FK_OFF;
    __half* Vs = hsm + FV_OFF;
    int*    mk = (int*)(hsm + FM_H);

    const int qt = blockIdx.x, h = blockIdx.y, b = blockIdx.z;
    const int tid = threadIdx.x, lane = tid & 31, warp = tid >> 5;
    const int lr = lane >> 2, lc = lane & 3;
    const int fr = lane & 15, fc = (lane >> 4) << 3;
    const size_t rb = (size_t)b * SEQ;
    const int hb = h * DK;
    const int q0 = qt * 128;

    int qrow[4], qch[4], krow[2], kch[2];
    #pragma unroll
    for (int l = 0; l < 4; l++) {
        int idx = tid + l * 256;
        qrow[l] = idx >> 3; qch[l] = idx & 7;
    }
    #pragma unroll
    for (int l = 0; l < 2; l++) {
        int idx = tid + l * 256;
        krow[l] = idx >> 3; kch[l] = idx & 7;
    }

    #pragma unroll
    for (int l = 0; l < 4; l++)
        cp16(&Qs[HSW(qrow[l], qch[l]*8)], Q + (rb + q0 + qrow[l])*D_MODEL + hb + qch[l]*8);
    #pragma unroll
    for (int l = 0; l < 2; l++) {
        cp16(&Ks[HSW(krow[l], kch[l]*8)], Kg + (rb + krow[l])*D_MODEL + hb + kch[l]*8);
        cp16(&Vs[HSW(krow[l], kch[l]*8)], Vg + (rb + krow[l])*D_MODEL + hb + kch[l]*8);
    }
    if (tid < 16) cp16(&mk[tid*4], mask + b*SEQ + tid*4);
    asm volatile("cp.async.commit_group;");
    asm volatile("cp.async.wait_group 0;");
    __syncthreads();

    unsigned qf[4][4];
    {
        const __half2 s8 = __float2half2_rn(0.125f);
        #pragma unroll
        for (int s = 0; s < 4; s++) {
            ldsm4(qf[s][0], qf[s][1], qf[s][2], qf[s][3],
                  &Qs[HSW(warp*16 + fr, s*16 + fc)]);
            #pragma unroll
            for (int r = 0; r < 4; r++) {
                __half2 t = *(__half2*)&qf[s][r];
                t = __hmul2(t, s8);
                qf[s][r] = *(unsigned*)&t;
            }
        }
    }

    float oacc[8][4] = {};
    float m0 = -1e30f, m1 = -1e30f, l0 = 0.f, l1 = 0.f;

    for (int kt = 0; kt < FL_NT; kt++) {
        const int cur = kt & 1, nxt = cur ^ 1;

        if (kt + 1 < FL_NT) {
            const int k0n = (kt + 1) * 64;
            #pragma unroll
            for (int l = 0; l < 2; l++) {
                cp16(&Ks[nxt*4096 + HSW(krow[l], kch[l]*8)],
                     Kg + (rb + k0n + krow[l])*D_MODEL + hb + kch[l]*8);
                cp16(&Vs[nxt*4096 + HSW(krow[l], kch[l]*8)],
                     Vg + (rb + k0n + krow[l])*D_MODEL + hb + kch[l]*8);
            }
            if (tid < 16) cp16(&mk[nxt*64 + tid*4], mask + b*SEQ + k0n + tid*4);
            asm volatile("cp.async.commit_group;");
            asm volatile("cp.async.wait_group 1;");
        } else {
            asm volatile("cp.async.wait_group 0;");
        }
        __syncthreads();

        const __half* Kc = Ks + cur*4096;
        const __half* Vc = Vs + cur*4096;
        const int*    mc = mk + cur*64;

        float sa[8][4] = {};
        #pragma unroll
        for (int s = 0; s < 4; s++) {
            #pragma unroll
            for (int jj = 0; jj < 4; jj++) {
                unsigned r0, r1, r2, r3;
                ldsm4(r0, r1, r2, r3, &Kc[HSW(jj*16 + fr, s*16 + fc)]);
                mma16816(sa[2*jj],   qf[s], r0, r2);
                mma16816(sa[2*jj+1], qf[s], r1, r3);
            }
        }

        float mx0 = m0, mx1 = m1;
        #pragma unroll
        for (int nb = 0; nb < 8; nb++) {
            int2 mm = *(const int2*)&mc[nb*8 + 2*lc];
            float b0 = (mm.x == 1) ? -1e30f : 0.f;
            float b1 = (mm.y == 1) ? -1e30f : 0.f;
            sa[nb][0] += b0; sa[nb][1] += b1;
            sa[nb][2] += b0; sa[nb][3] += b1;
            mx0 = fmaxf(mx0, fmaxf(sa[nb][0], sa[nb][1]));
            mx1 = fmaxf(mx1, fmaxf(sa[nb][2], sa[nb][3]));
        }
        mx0 = fmaxf(mx0, __shfl_xor_sync(0xffffffffu, mx0, 1));
        mx0 = fmaxf(mx0, __shfl_xor_sync(0xffffffffu, mx0, 2));
        mx1 = fmaxf(mx1, __shfl_xor_sync(0xffffffffu, mx1, 1));
        mx1 = fmaxf(mx1, __shfl_xor_sync(0xffffffffu, mx1, 2));

        const float corr0 = __expf(m0 - mx0);
        const float corr1 = __expf(m1 - mx1);
        float sum0 = 0.f, sum1 = 0.f;
        #pragma unroll
        for (int nb = 0; nb < 8; nb++) {
            sa[nb][0] = __expf(sa[nb][0] - mx0);
            sa[nb][1] = __expf(sa[nb][1] - mx0);
            sa[nb][2] = __expf(sa[nb][2] - mx1);
            sa[nb][3] = __expf(sa[nb][3] - mx1);
            sum0 += sa[nb][0] + sa[nb][1];
            sum1 += sa[nb][2] + sa[nb][3];
        }
        sum0 += __shfl_xor_sync(0xffffffffu, sum0, 1);
        sum0 += __shfl_xor_sync(0xffffffffu, sum0, 2);
        sum1 += __shfl_xor_sync(0xffffffffu, sum1, 1);
        sum1 += __shfl_xor_sync(0xffffffffu, sum1, 2);
        l0 = l0 * corr0 + sum0; m0 = mx0;
        l1 = l1 * corr1 + sum1; m1 = mx1;

        #pragma unroll
        for (int d = 0; d < 8; d++) {
            oacc[d][0] *= corr0; oacc[d][1] *= corr0;
            oacc[d][2] *= corr1; oacc[d][3] *= corr1;
        }

        #pragma unroll
        for (int s = 0; s < 4; s++) {
            unsigned pa[4];
            pa[0] = pack_h2(sa[2*s][0],   sa[2*s][1]);
            pa[1] = pack_h2(sa[2*s][2],   sa[2*s][3]);
            pa[2] = pack_h2(sa[2*s+1][0], sa[2*s+1][1]);
            pa[3] = pack_h2(sa[2*s+1][2], sa[2*s+1][3]);
            #pragma unroll
            for (int dp = 0; dp < 4; dp++) {
                unsigned r0, r1, r2, r3;
                ldsm4t(r0, r1, r2, r3, &Vc[HSW(s*16 + fr, dp*16 + fc)]);
                mma16816(oacc[2*dp],   pa, r0, r1);
                mma16816(oacc[2*dp+1], pa, r2, r3);
            }
        }
        __syncthreads();
    }

    const float inv0 = 1.0f / l0, inv1 = 1.0f / l1;
    const int row = q0 + warp*16 + lr;
    __half* OA = O + (rb + row) * D_MODEL + hb;
    __half* OB = OA + 8 * D_MODEL;
    #pragma unroll
    for (int d = 0; d < 8; d++) {
        *(__half2*)(OA + d*8 + 2*lc) = __floats2half2_rn(oacc[d][0]*inv0, oacc[d][1]*inv0);
        *(__half2*)(OB + d*8 + 2*lc) = __floats2half2_rn(oacc[d][2]*inv1, oacc[d][3]*inv1);
    }
}

// ---------------- orchestration ---------------------------------------------
extern "C" void kernel_launch(void* const* d_in, const int* in_sizes, int n_in,
                              void* d_out, int out_size)
{
    const float* x      = (const float*)d_in[0];
    const int*   mask   = (const int*)  d_in[1];
    const float* alpha1 = (const float*)d_in[2];
    const float* bias1  = (const float*)d_in[3];
    const float* alpha2 = (const float*)d_in[4];
    const float* bias2  = (const float*)d_in[5];
    const float* Wq = (const float*)d_in[6];   const float* bq = (const float*)d_in[7];
    const float* Wk = (const float*)d_in[8];   const float* bk = (const float*)d_in[9];
    const float* Wv = (const float*)d_in[10];  const float* bv = (const float*)d_in[11];
    const float* Wo = (const float*)d_in[12];  const float* bo = (const float*)d_in[13];
    const float* W1 = (const float*)d_in[14];  const float* b1 = (const float*)d_in[15];
    const float* W2 = (const float*)d_in[16];  const float* b2 = (const float*)d_in[17];
    float* out = (float*)d_out;

    __half *x2h, *qh, *kh, *vh, *attnh, *hh;
    __half *Wqkvh, *Woh, *W1h, *W2h;
    float  *xres;
    cudaGetSymbolAddress((void**)&x2h,   g_x2h);
    cudaGetSymbolAddress((void**)&qh,    g_qh);
    cudaGetSymbolAddress((void**)&kh,    g_kh);
    cudaGetSymbolAddress((void**)&vh,    g_vh);
    cudaGetSymbolAddress((void**)&attnh, g_attnh);
    cudaGetSymbolAddress((void**)&hh,    g_hh);
    cudaGetSymbolAddress((void**)&xres,  g_xres);
    cudaGetSymbolAddress((void**)&Wqkvh, g_Wqkvh);
    cudaGetSymbolAddress((void**)&Woh,   g_Woh);
    cudaGetSymbolAddress((void**)&W1h,   g_W1h);
    cudaGetSymbolAddress((void**)&W2h,   g_W2h);

    cudaFuncSetAttribute(flash_kernel,
                         cudaFuncAttributeMaxDynamicSharedMemorySize, FL_SMEM_BYTES);
    cudaFuncSetAttribute(hgemm_qkv_kernel,
                         cudaFuncAttributeMaxDynamicSharedMemorySize, HG_SMEM_BYTES);
    cudaFuncSetAttribute(hgemm_kernel<false, true, false>,
                         cudaFuncAttributeMaxDynamicSharedMemorySize, HG_SMEM_BYTES);
    cudaFuncSetAttribute(hgemm_kernel<true, false, true>,
                         cudaFuncAttributeMaxDynamicSharedMemorySize, HG_SMEM_BYTES);

    // L1: Wq|Wk|Wv -> concatenated fp16   L2: Wo, W1, W2 -> fp16
    f2h_qkv_kernel<<<3 * NP4 / 256, 256>>>(
        (const float4*)Wq, (const float4*)Wk, (const float4*)Wv, (H2X2*)Wqkvh);
    f2h_rest_kernel<<<(NP4 + 2 * NF4) / 256, 256>>>(
        (const float4*)Wo, (const float4*)W1, (const float4*)W2,
        (H2X2*)Woh, (H2X2*)W1h, (H2X2*)W2h);

    const dim3 gQKV(3 * D_MODEL / 128, ROWS / 128);   // (24, 64)
    const dim3 gProj(D_MODEL / 128, ROWS / 128);      // (8, 64)
    const dim3 gFF1 (D_FF    / 128, ROWS / 128);      // (16, 64)

    // L3
    norm_kernel<<<ROWS, 256>>>(x, alpha1, bias1, x2h);
    // L4: fused QKV
    hgemm_qkv_kernel<<<gQKV, 256, HG_SMEM_BYTES>>>(
        x2h, Wqkvh, bq, bk, bv, qh, kh, vh);
    // L5
    flash_kernel<<<dim3(SEQ / 128, HEADS, BATCH), 256, FL_SMEM_BYTES>>>(
        qh, kh, vh, mask, attnh);
    // L6 (ncu -s 5 -c 1 captures this one)
    hgemm_kernel<false, true, false><<<gProj, 256, HG_SMEM_BYTES>>>(
        attnh, Woh, bo, x, xres, nullptr, ROWS, D_MODEL, D_MODEL);
    // L7
    norm_kernel<<<ROWS, 256>>>(xres, alpha2, bias2, x2h);
    // L8
    hgemm_kernel<true, false, true><<<gFF1, 256, HG_SMEM_BYTES>>>(
        x2h, W1h, b1, nullptr, nullptr, hh, ROWS, D_FF, D_MODEL);
    // L9
    hgemm_kernel<false, true, false><<<gProj, 256, HG_SMEM_BYTES>>>(
        hh, W2h, b2, xres, out, nullptr, ROWS, D_MODEL, D_FF);
}

// round 17
// speedup vs baseline: 8.3418x; 1.0068x over previous
#include <cuda_runtime.h>
#include <cuda_fp16.h>
#include <math.h>

#define D_MODEL 1024
#define D_FF    2048
#define BATCH   4
#define SEQ     2048
#define HEADS   16
#define DK      64
#define ROWS    (BATCH * SEQ)   // 8192

// ---------------- scratch (no allocs allowed -> __device__ globals) ----------
__device__ __half g_x2h [ROWS * D_MODEL];
__device__ __half g_qh  [ROWS * D_MODEL];
__device__ __half g_kh  [ROWS * D_MODEL];
__device__ __half g_vh  [ROWS * D_MODEL];
__device__ __half g_attnh[ROWS * D_MODEL];
__device__ __half g_hh  [ROWS * D_FF];
__device__ float  g_xres[ROWS * D_MODEL];
__device__ __half g_Wqkvh[3 * D_MODEL * D_MODEL];
__device__ __half g_Woh[D_MODEL * D_MODEL];
__device__ __half g_W1h[D_FF * D_MODEL];
__device__ __half g_W2h[D_MODEL * D_FF];

struct __align__(8) H2X2 { __half2 a, b; };

// ---------------- helpers ----------------------------------------------------
__device__ __forceinline__ void cp16(void* s, const void* g) {
    unsigned sa = (unsigned)__cvta_generic_to_shared(s);
    asm volatile("cp.async.cg.shared.global [%0], [%1], 16;" :: "r"(sa), "l"(g));
}
__device__ __forceinline__ void cp16s(unsigned sa, const void* g) {
    asm volatile("cp.async.cg.shared.global [%0], [%1], 16;" :: "r"(sa), "l"(g));
}

__device__ __forceinline__ void ldsm4(unsigned& r0, unsigned& r1,
                                      unsigned& r2, unsigned& r3, const void* p) {
    unsigned a = (unsigned)__cvta_generic_to_shared(p);
    asm volatile("ldmatrix.sync.aligned.m8n8.x4.shared.b16 {%0,%1,%2,%3}, [%4];"
                 : "=r"(r0), "=r"(r1), "=r"(r2), "=r"(r3) : "r"(a));
}
__device__ __forceinline__ void ldsm4a(unsigned& r0, unsigned& r1,
                                       unsigned& r2, unsigned& r3, unsigned a) {
    asm volatile("ldmatrix.sync.aligned.m8n8.x4.shared.b16 {%0,%1,%2,%3}, [%4];"
                 : "=r"(r0), "=r"(r1), "=r"(r2), "=r"(r3) : "r"(a));
}

__device__ __forceinline__ void ldsm4t(unsigned& r0, unsigned& r1,
                                       unsigned& r2, unsigned& r3, const void* p) {
    unsigned a = (unsigned)__cvta_generic_to_shared(p);
    asm volatile("ldmatrix.sync.aligned.m8n8.x4.trans.shared.b16 {%0,%1,%2,%3}, [%4];"
                 : "=r"(r0), "=r"(r1), "=r"(r2), "=r"(r3) : "r"(a));
}

__device__ __forceinline__ void mma16816(float* d, const unsigned* a,
                                         unsigned b0, unsigned b1) {
    asm volatile(
        "mma.sync.aligned.m16n8k16.row.col.f32.f16.f16.f32 "
        "{%0,%1,%2,%3}, {%4,%5,%6,%7}, {%8,%9}, {%0,%1,%2,%3};"
        : "+f"(d[0]), "+f"(d[1]), "+f"(d[2]), "+f"(d[3])
        : "r"(a[0]), "r"(a[1]), "r"(a[2]), "r"(a[3]), "r"(b0), "r"(b1));
}

__device__ __forceinline__ unsigned pack_h2(float lo, float hi) {
    __half2 h = __floats2half2_rn(lo, hi);
    return *(unsigned*)&h;
}

// swizzled smem layout for 64-half (128B) rows
#define HSW(r, c) ((r) * 64 + ((((c) >> 3) ^ ((r) & 7)) << 3) + ((c) & 7))

// ---------------- fused fp32 -> fp16 weight conversion ------------------------
#define NP4 (D_MODEL * D_MODEL / 4)
#define NF4 (D_FF * D_MODEL / 4)

__device__ __forceinline__ H2X2 f2h4(float4 v) {
    H2X2 o;
    o.a = __floats2half2_rn(v.x, v.y);
    o.b = __floats2half2_rn(v.z, v.w);
    return o;
}

__global__ void f2h_qkv_kernel(const float4* __restrict__ Wq,
                               const float4* __restrict__ Wk,
                               const float4* __restrict__ Wv,
                               H2X2* __restrict__ dst) {
    int i = blockIdx.x * blockDim.x + threadIdx.x;
    int w = i / NP4, j = i - w * NP4;
    const float4* src = (w == 0) ? Wq : (w == 1) ? Wk : Wv;
    dst[i] = f2h4(src[j]);
}

__global__ void f2h_rest_kernel(const float4* __restrict__ Wo,
                                const float4* __restrict__ W1,
                                const float4* __restrict__ W2,
                                H2X2* __restrict__ dWo, H2X2* __restrict__ dW1,
                                H2X2* __restrict__ dW2) {
    int i = blockIdx.x * blockDim.x + threadIdx.x;
    if (i < NP4) {
        dWo[i] = f2h4(Wo[i]);
    } else if (i < NP4 + NF4) {
        dW1[i - NP4] = f2h4(W1[i - NP4]);
    } else {
        dW2[i - NP4 - NF4] = f2h4(W2[i - NP4 - NF4]);
    }
}

// ---------------- LayerNorm (fp32 in, fp16 out) ------------------------------
__global__ void __launch_bounds__(256) norm_kernel(
    const float* __restrict__ x, const float* __restrict__ alpha,
    const float* __restrict__ bias, __half* __restrict__ out)
{
    const int row = blockIdx.x;
    const int t = threadIdx.x;
    const float4* xr = (const float4*)(x + (size_t)row * D_MODEL);
    float4 v = xr[t];
    float s  = v.x + v.y + v.z + v.w;
    float ss = v.x*v.x + v.y*v.y + v.z*v.z + v.w*v.w;
    #pragma unroll
    for (int o = 16; o; o >>= 1) {
        s  += __shfl_xor_sync(0xffffffffu, s, o);
        ss += __shfl_xor_sync(0xffffffffu, ss, o);
    }
    __shared__ float rs[8], rss[8];
    __shared__ float s_mu, s_inv;
    const int w = t >> 5, l = t & 31;
    if (l == 0) { rs[w] = s; rss[w] = ss; }
    __syncthreads();
    if (t == 0) {
        float S = 0.f, SS = 0.f;
        #pragma unroll
        for (int i = 0; i < 8; i++) { S += rs[i]; SS += rss[i]; }
        float mu  = S * (1.0f / D_MODEL);
        float var = (SS - (float)D_MODEL * mu * mu) * (1.0f / (D_MODEL - 1));
        s_mu  = mu;
        s_inv = 1.0f / (sqrtf(fmaxf(var, 0.f)) + 1e-6f);
    }
    __syncthreads();
    const float mu = s_mu, inv = s_inv;
    float4 av = ((const float4*)alpha)[t];
    float4 bv = ((const float4*)bias)[t];
    H2X2 o;
    o.a = __floats2half2_rn(av.x * (v.x - mu) * inv + bv.x,
                            av.y * (v.y - mu) * inv + bv.y);
    o.b = __floats2half2_rn(av.z * (v.z - mu) * inv + bv.z,
                            av.w * (v.w - mu) * inv + bv.w);
    ((H2X2*)(out + (size_t)row * D_MODEL))[t] = o;
}

// ---------------- fp16 tensor-core GEMM (3-stage, hoisted addressing) ---------
// CTA 128x128, k-chunk 64, 8 warps (2Mx4N), warp 64x32, mma m16n8k16.
// 3 pipeline stages, ONE __syncthreads per k-iteration. All smem addresses
// precomputed per-thread (swizzle perm is thread-invariant across rows/stages).
#define HG_STG_H   16384                  // halfs per stage (A 8192 | B 8192)
#define HG_STG_B   (HG_STG_H * 2)         // 32KB
#define HG_SMEM_BYTES (3 * HG_STG_B)      // 96KB

// body shared by plain + qkv variants; epilogue differs.
#define HGEMM_MAIN(A_PTR, W_PTR, K_)                                           \
    extern __shared__ __half hsm[];                                            \
    const unsigned sbase = (unsigned)__cvta_generic_to_shared(hsm);            \
    const int tid  = threadIdx.x;                                              \
    const int lane = tid & 31;                                                 \
    const int warp = tid >> 5;                                                 \
    const int wm = warp >> 2;                                                  \
    const int wn = warp & 3;                                                   \
    unsigned swoff[4];                                                         \
    const __half* gA[4];                                                       \
    const __half* gB[4];                                                       \
    _Pragma("unroll")                                                          \
    for (int l = 0; l < 4; l++) {                                              \
        int idx = tid + l * 256;                                               \
        int r = idx >> 3, ch = idx & 7;                                        \
        swoff[l] = HSW(r, ch * 8) * 2;                                         \
        gA[l] = (A_PTR) + (size_t)(m0 + r) * (K_) + ch * 8;                    \
        gB[l] = (W_PTR) + (size_t)(n0 + r) * (K_) + ch * 8;                    \
    }                                                                          \
    const int fr  = lane & 15;                                                 \
    const int fc8 = lane >> 4;                                                 \
    unsigned offs[4];                                                          \
    _Pragma("unroll")                                                          \
    for (int s = 0; s < 4; s++)                                                \
        offs[s] = ((((s * 2 + fc8) ^ (fr & 7)) << 3) << 1);                    \
    unsigned rbA[4], rbB[2];                                                   \
    _Pragma("unroll")                                                          \
    for (int i = 0; i < 4; i++) rbA[i] = (wm*64 + i*16 + fr) * 128;            \
    _Pragma("unroll")                                                          \
    for (int j = 0; j < 2; j++) rbB[j] = 16384 + (wn*32 + j*16 + fr) * 128;    \
    const int KT = (K_) >> 6;                                                  \
    auto load_stage = [&](int st, int koff) {                                  \
        unsigned sb = sbase + st * HG_STG_B;                                   \
        _Pragma("unroll")                                                      \
        for (int l = 0; l < 4; l++) {                                          \
            cp16s(sb + swoff[l],         gA[l] + koff);                        \
            cp16s(sb + 16384 + swoff[l], gB[l] + koff);                        \
        }                                                                      \
        asm volatile("cp.async.commit_group;");                                \
    };                                                                         \
    load_stage(0, 0);                                                          \
    load_stage(1, 64);                                                         \
    float acc[4][4][4] = {};                                                   \
    for (int kt = 0; kt < KT; kt++) {                                          \
        if (kt + 1 < KT) asm volatile("cp.async.wait_group 1;");               \
        else             asm volatile("cp.async.wait_group 0;");               \
        __syncthreads();                                                       \
        if (kt + 2 < KT) {                                                     \
            load_stage((kt + 2) % 3, (kt + 2) << 6);                           \
        }                                                                      \
        unsigned sb = sbase + (kt % 3) * HG_STG_B;                             \
        _Pragma("unroll")                                                      \
        for (int s = 0; s < 4; s++) {                                          \
            unsigned af[4][4];                                                 \
            _Pragma("unroll")                                                  \
            for (int i = 0; i < 4; i++)                                        \
                ldsm4a(af[i][0], af[i][1], af[i][2], af[i][3],                 \
                       sb + rbA[i] + offs[s]);                                 \
            unsigned bfr[4][2];                                                \
            _Pragma("unroll")                                                  \
            for (int j = 0; j < 2; j++) {                                      \
                unsigned r0, r1, r2, r3;                                       \
                ldsm4a(r0, r1, r2, r3, sb + rbB[j] + offs[s]);                 \
                bfr[2*j][0]   = r0; bfr[2*j][1]   = r2;                        \
                bfr[2*j+1][0] = r1; bfr[2*j+1][1] = r3;                        \
            }                                                                  \
            _Pragma("unroll")                                                  \
            for (int i = 0; i < 4; i++)                                        \
                _Pragma("unroll")                                              \
                for (int j = 0; j < 4; j++)                                    \
                    mma16816(acc[i][j], af[i], bfr[j][0], bfr[j][1]);          \
        }                                                                      \
    }

template<bool RELU, bool RES, bool HOUT>
__global__ void __launch_bounds__(256, 2) hgemm_kernel(
    const __half* __restrict__ A, const __half* __restrict__ W,
    const float* __restrict__ bias, const float* __restrict__ R,
    float* __restrict__ C, __half* __restrict__ Ch, int M, int N, int K)
{
    const int m0 = blockIdx.y * 128, n0 = blockIdx.x * 128;
    HGEMM_MAIN(A, W, K)

    const int lr = lane >> 2, lc = lane & 3;
    #pragma unroll
    for (int i = 0; i < 4; i++) {
        const int m = m0 + wm*64 + i*16 + lr;
        #pragma unroll
        for (int j = 0; j < 4; j++) {
            const int n = n0 + wn*32 + j*8 + lc*2;
            const float bx = bias[n], by = bias[n + 1];
            float v0 = acc[i][j][0] + bx, v1 = acc[i][j][1] + by;
            float v2 = acc[i][j][2] + bx, v3 = acc[i][j][3] + by;
            if (RELU) {
                v0 = fmaxf(v0, 0.f); v1 = fmaxf(v1, 0.f);
                v2 = fmaxf(v2, 0.f); v3 = fmaxf(v3, 0.f);
            }
            if (RES) {
                float2 r0 = *(const float2*)(R + (size_t)m*N + n);
                float2 r1 = *(const float2*)(R + (size_t)(m+8)*N + n);
                v0 += r0.x; v1 += r0.y; v2 += r1.x; v3 += r1.y;
            }
            if (HOUT) {
                *(__half2*)(Ch + (size_t)m*N + n)     = __floats2half2_rn(v0, v1);
                *(__half2*)(Ch + (size_t)(m+8)*N + n) = __floats2half2_rn(v2, v3);
            } else {
                *(float2*)(C + (size_t)m*N + n)     = make_float2(v0, v1);
                *(float2*)(C + (size_t)(m+8)*N + n) = make_float2(v2, v3);
            }
        }
    }
}

// fused QKV: N=3072 vs concatenated Wqkv; CTA column block selects q/k/v.
__global__ void __launch_bounds__(256, 2) hgemm_qkv_kernel(
    const __half* __restrict__ A, const __half* __restrict__ W,
    const float* __restrict__ bq, const float* __restrict__ bk,
    const float* __restrict__ bv,
    __half* __restrict__ Q, __half* __restrict__ Kh, __half* __restrict__ V)
{
    const int m0 = blockIdx.y * 128, n0 = blockIdx.x * 128;
    const int sel = blockIdx.x >> 3;
    const float* bias = (sel == 0) ? bq : (sel == 1) ? bk : bv;
    __half* Ch = (sel == 0) ? Q : (sel == 1) ? Kh : V;
    const int c0 = n0 & (D_MODEL - 1);

    HGEMM_MAIN(A, W, D_MODEL)

    const int lr = lane >> 2, lc = lane & 3;
    #pragma unroll
    for (int i = 0; i < 4; i++) {
        const int m = m0 + wm*64 + i*16 + lr;
        #pragma unroll
        for (int j = 0; j < 4; j++) {
            const int n = c0 + wn*32 + j*8 + lc*2;
            const float bx = bias[n], by = bias[n + 1];
            float v0 = acc[i][j][0] + bx, v1 = acc[i][j][1] + by;
            float v2 = acc[i][j][2] + bx, v3 = acc[i][j][3] + by;
            *(__half2*)(Ch + (size_t)m*D_MODEL + n)     = __floats2half2_rn(v0, v1);
            *(__half2*)(Ch + (size_t)(m+8)*D_MODEL + n) = __floats2half2_rn(v2, v3);
        }
    }
}

// ---------------- fp16 flash attention (unchanged this round) -----------------
#define FQ_OFF 0
#define FK_OFF 8192
#define FV_OFF 16384
#define FM_H   24576
#define FL_SMEM_BYTES (FM_H * 2 + 2 * 64 * 4)
#define FL_NT (SEQ / 64)

__global__ void __launch_bounds__(256, 2) flash_kernel(
    const __half* __restrict__ Q, const __half* __restrict__ Kg,
    const __half* __restrict__ Vg, const int* __restrict__ mask,
    __half* __restrict__ O)
{
    extern __shared__ __half hsm[];
    __half* Qs = hsm + FQ_OFF;
    __half* Ks = hsm + FK_OFF;
    __half* Vs = hsm + FV_OFF;
    int*    mk = (int*)(hsm + FM_H);

    const int qt = blockIdx.x, h = blockIdx.y, b = blockIdx.z;
    const int tid = threadIdx.x, lane = tid & 31, warp = tid >> 5;
    const int lr = lane >> 2, lc = lane & 3;
    const int fr = lane & 15, fc = (lane >> 4) << 3;
    const size_t rb = (size_t)b * SEQ;
    const int hb = h * DK;
    const int q0 = qt * 128;

    int qrow[4], qch[4], krow[2], kch[2];
    #pragma unroll
    for (int l = 0; l < 4; l++) {
        int idx = tid + l * 256;
        qrow[l] = idx >> 3; qch[l] = idx & 7;
    }
    #pragma unroll
    for (int l = 0; l < 2; l++) {
        int idx = tid + l * 256;
        krow[l] = idx >> 3; kch[l] = idx & 7;
    }

    #pragma unroll
    for (int l = 0; l < 4; l++)
        cp16(&Qs[HSW(qrow[l], qch[l]*8)], Q + (rb + q0 + qrow[l])*D_MODEL + hb + qch[l]*8);
    #pragma unroll
    for (int l = 0; l < 2; l++) {
        cp16(&Ks[HSW(krow[l], kch[l]*8)], Kg + (rb + krow[l])*D_MODEL + hb + kch[l]*8);
        cp16(&Vs[HSW(krow[l], kch[l]*8)], Vg + (rb + krow[l])*D_MODEL + hb + kch[l]*8);
    }
    if (tid < 16) cp16(&mk[tid*4], mask + b*SEQ + tid*4);
    asm volatile("cp.async.commit_group;");
    asm volatile("cp.async.wait_group 0;");
    __syncthreads();

    unsigned qf[4][4];
    {
        const __half2 s8 = __float2half2_rn(0.125f);
        #pragma unroll
        for (int s = 0; s < 4; s++) {
            ldsm4(qf[s][0], qf[s][1], qf[s][2], qf[s][3],
                  &Qs[HSW(warp*16 + fr, s*16 + fc)]);
            #pragma unroll
            for (int r = 0; r < 4; r++) {
                __half2 t = *(__half2*)&qf[s][r];
                t = __hmul2(t, s8);
                qf[s][r] = *(unsigned*)&t;
            }
        }
    }

    float oacc[8][4] = {};
    float m0 = -1e30f, m1 = -1e30f, l0 = 0.f, l1 = 0.f;

    for (int kt = 0; kt < FL_NT; kt++) {
        const int cur = kt & 1, nxt = cur ^ 1;

        if (kt + 1 < FL_NT) {
            const int k0n = (kt + 1) * 64;
            #pragma unroll
            for (int l = 0; l < 2; l++) {
                cp16(&Ks[nxt*4096 + HSW(krow[l], kch[l]*8)],
                     Kg + (rb + k0n + krow[l])*D_MODEL + hb + kch[l]*8);
                cp16(&Vs[nxt*4096 + HSW(krow[l], kch[l]*8)],
                     Vg + (rb + k0n + krow[l])*D_MODEL + hb + kch[l]*8);
            }
            if (tid < 16) cp16(&mk[nxt*64 + tid*4], mask + b*SEQ + k0n + tid*4);
            asm volatile("cp.async.commit_group;");
            asm volatile("cp.async.wait_group 1;");
        } else {
            asm volatile("cp.async.wait_group 0;");
        }
        __syncthreads();

        const __half* Kc = Ks + cur*4096;
        const __half* Vc = Vs + cur*4096;
        const int*    mc = mk + cur*64;

        float sa[8][4] = {};
        #pragma unroll
        for (int s = 0; s < 4; s++) {
            #pragma unroll
            for (int jj = 0; jj < 4; jj++) {
                unsigned r0, r1, r2, r3;
                ldsm4(r0, r1, r2, r3, &Kc[HSW(jj*16 + fr, s*16 + fc)]);
                mma16816(sa[2*jj],   qf[s], r0, r2);
                mma16816(sa[2*jj+1], qf[s], r1, r3);
            }
        }

        float mx0 = m0, mx1 = m1;
        #pragma unroll
        for (int nb = 0; nb < 8; nb++) {
            int2 mm = *(const int2*)&mc[nb*8 + 2*lc];
            float b0 = (mm.x == 1) ? -1e30f : 0.f;
            float b1 = (mm.y == 1) ? -1e30f : 0.f;
            sa[nb][0] += b0; sa[nb][1] += b1;
            sa[nb][2] += b0; sa[nb][3] += b1;
            mx0 = fmaxf(mx0, fmaxf(sa[nb][0], sa[nb][1]));
            mx1 = fmaxf(mx1, fmaxf(sa[nb][2], sa[nb][3]));
        }
        mx0 = fmaxf(mx0, __shfl_xor_sync(0xffffffffu, mx0, 1));
        mx0 = fmaxf(mx0, __shfl_xor_sync(0xffffffffu, mx0, 2));
        mx1 = fmaxf(mx1, __shfl_xor_sync(0xffffffffu, mx1, 1));
        mx1 = fmaxf(mx1, __shfl_xor_sync(0xffffffffu, mx1, 2));

        const float corr0 = __expf(m0 - mx0);
        const float corr1 = __expf(m1 - mx1);
        float sum0 = 0.f, sum1 = 0.f;
        #pragma unroll
        for (int nb = 0; nb < 8; nb++) {
            sa[nb][0] = __expf(sa[nb][0] - mx0);
            sa[nb][1] = __expf(sa[nb][1] - mx0);
            sa[nb][2] = __expf(sa[nb][2] - mx1);
            sa[nb][3] = __expf(sa[nb][3] - mx1);
            sum0 += sa[nb][0] + sa[nb][1];
            sum1 += sa[nb][2] + sa[nb][3];
        }
        sum0 += __shfl_xor_sync(0xffffffffu, sum0, 1);
        sum0 += __shfl_xor_sync(0xffffffffu, sum0, 2);
        sum1 += __shfl_xor_sync(0xffffffffu, sum1, 1);
        sum1 += __shfl_xor_sync(0xffffffffu, sum1, 2);
        l0 = l0 * corr0 + sum0; m0 = mx0;
        l1 = l1 * corr1 + sum1; m1 = mx1;

        #pragma unroll
        for (int d = 0; d < 8; d++) {
            oacc[d][0] *= corr0; oacc[d][1] *= corr0;
            oacc[d][2] *= corr1; oacc[d][3] *= corr1;
        }

        #pragma unroll
        for (int s = 0; s < 4; s++) {
            unsigned pa[4];
            pa[0] = pack_h2(sa[2*s][0],   sa[2*s][1]);
            pa[1] = pack_h2(sa[2*s][2],   sa[2*s][3]);
            pa[2] = pack_h2(sa[2*s+1][0], sa[2*s+1][1]);
            pa[3] = pack_h2(sa[2*s+1][2], sa[2*s+1][3]);
            #pragma unroll
            for (int dp = 0; dp < 4; dp++) {
                unsigned r0, r1, r2, r3;
                ldsm4t(r0, r1, r2, r3, &Vc[HSW(s*16 + fr, dp*16 + fc)]);
                mma16816(oacc[2*dp],   pa, r0, r1);
                mma16816(oacc[2*dp+1], pa, r2, r3);
            }
        }
        __syncthreads();
    }

    const float inv0 = 1.0f / l0, inv1 = 1.0f / l1;
    const int row = q0 + warp*16 + lr;
    __half* OA = O + (rb + row) * D_MODEL + hb;
    __half* OB = OA + 8 * D_MODEL;
    #pragma unroll
    for (int d = 0; d < 8; d++) {
        *(__half2*)(OA + d*8 + 2*lc) = __floats2half2_rn(oacc[d][0]*inv0, oacc[d][1]*inv0);
        *(__half2*)(OB + d*8 + 2*lc) = __floats2half2_rn(oacc[d][2]*inv1, oacc[d][3]*inv1);
    }
}

// ---------------- orchestration ---------------------------------------------
extern "C" void kernel_launch(void* const* d_in, const int* in_sizes, int n_in,
                              void* d_out, int out_size)
{
    const float* x      = (const float*)d_in[0];
    const int*   mask   = (const int*)  d_in[1];
    const float* alpha1 = (const float*)d_in[2];
    const float* bias1  = (const float*)d_in[3];
    const float* alpha2 = (const float*)d_in[4];
    const float* bias2  = (const float*)d_in[5];
    const float* Wq = (const float*)d_in[6];   const float* bq = (const float*)d_in[7];
    const float* Wk = (const float*)d_in[8];   const float* bk = (const float*)d_in[9];
    const float* Wv = (const float*)d_in[10];  const float* bv = (const float*)d_in[11];
    const float* Wo = (const float*)d_in[12];  const float* bo = (const float*)d_in[13];
    const float* W1 = (const float*)d_in[14];  const float* b1 = (const float*)d_in[15];
    const float* W2 = (const float*)d_in[16];  const float* b2 = (const float*)d_in[17];
    float* out = (float*)d_out;

    __half *x2h, *qh, *kh, *vh, *attnh, *hh;
    __half *Wqkvh, *Woh, *W1h, *W2h;
    float  *xres;
    cudaGetSymbolAddress((void**)&x2h,   g_x2h);
    cudaGetSymbolAddress((void**)&qh,    g_qh);
    cudaGetSymbolAddress((void**)&kh,    g_kh);
    cudaGetSymbolAddress((void**)&vh,    g_vh);
    cudaGetSymbolAddress((void**)&attnh, g_attnh);
    cudaGetSymbolAddress((void**)&hh,    g_hh);
    cudaGetSymbolAddress((void**)&xres,  g_xres);
    cudaGetSymbolAddress((void**)&Wqkvh, g_Wqkvh);
    cudaGetSymbolAddress((void**)&Woh,   g_Woh);
    cudaGetSymbolAddress((void**)&W1h,   g_W1h);
    cudaGetSymbolAddress((void**)&W2h,   g_W2h);

    cudaFuncSetAttribute(flash_kernel,
                         cudaFuncAttributeMaxDynamicSharedMemorySize, FL_SMEM_BYTES);
    cudaFuncSetAttribute(hgemm_qkv_kernel,
                         cudaFuncAttributeMaxDynamicSharedMemorySize, HG_SMEM_BYTES);
    cudaFuncSetAttribute(hgemm_kernel<false, true, false>,
                         cudaFuncAttributeMaxDynamicSharedMemorySize, HG_SMEM_BYTES);
    cudaFuncSetAttribute(hgemm_kernel<true, false, true>,
                         cudaFuncAttributeMaxDynamicSharedMemorySize, HG_SMEM_BYTES);

    f2h_qkv_kernel<<<3 * NP4 / 256, 256>>>(
        (const float4*)Wq, (const float4*)Wk, (const float4*)Wv, (H2X2*)Wqkvh);
    f2h_rest_kernel<<<(NP4 + 2 * NF4) / 256, 256>>>(
        (const float4*)Wo, (const float4*)W1, (const float4*)W2,
        (H2X2*)Woh, (H2X2*)W1h, (H2X2*)W2h);

    const dim3 gQKV(3 * D_MODEL / 128, ROWS / 128);
    const dim3 gProj(D_MODEL / 128, ROWS / 128);
    const dim3 gFF1 (D_FF    / 128, ROWS / 128);

    norm_kernel<<<ROWS, 256>>>(x, alpha1, bias1, x2h);
    hgemm_qkv_kernel<<<gQKV, 256, HG_SMEM_BYTES>>>(
        x2h, Wqkvh, bq, bk, bv, qh, kh, vh);
    flash_kernel<<<dim3(SEQ / 128, HEADS, BATCH), 256, FL_SMEM_BYTES>>>(
        qh, kh, vh, mask, attnh);
    hgemm_kernel<false, true, false><<<gProj, 256, HG_SMEM_BYTES>>>(
        attnh, Woh, bo, x, xres, nullptr, ROWS, D_MODEL, D_MODEL);
    norm_kernel<<<ROWS, 256>>>(xres, alpha2, bias2, x2h);
    hgemm_kernel<true, false, true><<<gFF1, 256, HG_SMEM_BYTES>>>(
        x2h, W1h, b1, nullptr, nullptr, hh, ROWS, D_FF, D_MODEL);
    hgemm_kernel<false, true, false><<<gProj, 256, HG_SMEM_BYTES>>>(
        hh, W2h, b2, xres, out, nullptr, ROWS, D_MODEL, D_FF);
}